// round 1
// baseline (speedup 1.0000x reference)
#include <cuda_runtime.h>
#include <math.h>

#define BB 2
#define SS 2048
#define DMODEL 1024
#define NH 16
#define NKH 4
#define HD 64
// N_REP = NH/NKH = 4

// Scratch (device globals: allocation-free)
__device__ float g_q[BB * SS * NH * HD];    // 16 MB
__device__ float g_k[BB * SS * NKH * HD];   // 4 MB
__device__ float g_v[BB * SS * NKH * HD];   // 4 MB
__device__ float g_o[BB * SS * NH * HD];    // 16 MB

// ---------------------------------------------------------------------------
// SGEMM: C[M,N] = A[M,K] @ B[K,N], all row-major.
// 64x64 tile, BK=16, 256 threads, 4x4 per thread. Requires M%64==0, N%64==0,
// K%16==0, K%4==0 (float4 loads).
// ---------------------------------------------------------------------------
__global__ __launch_bounds__(256) void sgemm_kernel(
    const float* __restrict__ A, const float* __restrict__ B,
    float* __restrict__ C, int M, int N, int K)
{
    __shared__ float As[16][64];  // As[k][m]
    __shared__ float Bs[16][64];  // Bs[k][n]

    const int tid = threadIdx.x;
    const int tx = tid & 15;       // 0..15 -> n quad
    const int ty = tid >> 4;       // 0..15 -> m quad
    const int bm = blockIdx.y * 64;
    const int bn = blockIdx.x * 64;

    // A load: row ar (0..63), k quad ak
    const int ar = tid >> 2;
    const int ak = (tid & 3) << 2;
    // B load: k row bk (0..15), n quad bnq
    const int bk = tid >> 4;
    const int bnq = (tid & 15) << 2;

    const float* Aptr = A + (size_t)(bm + ar) * K + ak;
    const float* Bptr = B + (size_t)bk * N + bn + bnq;

    float acc[4][4];
#pragma unroll
    for (int i = 0; i < 4; i++)
#pragma unroll
        for (int j = 0; j < 4; j++) acc[i][j] = 0.0f;

    for (int k0 = 0; k0 < K; k0 += 16) {
        float4 av = *(const float4*)(Aptr + k0);
        float4 bv = *(const float4*)(Bptr + (size_t)k0 * N);
        As[ak + 0][ar] = av.x;
        As[ak + 1][ar] = av.y;
        As[ak + 2][ar] = av.z;
        As[ak + 3][ar] = av.w;
        *(float4*)&Bs[bk][bnq] = bv;
        __syncthreads();

#pragma unroll
        for (int kk = 0; kk < 16; kk++) {
            float4 a = *(const float4*)&As[kk][ty * 4];
            float4 b = *(const float4*)&Bs[kk][tx * 4];
            acc[0][0] += a.x * b.x; acc[0][1] += a.x * b.y; acc[0][2] += a.x * b.z; acc[0][3] += a.x * b.w;
            acc[1][0] += a.y * b.x; acc[1][1] += a.y * b.y; acc[1][2] += a.y * b.z; acc[1][3] += a.y * b.w;
            acc[2][0] += a.z * b.x; acc[2][1] += a.z * b.y; acc[2][2] += a.z * b.z; acc[2][3] += a.z * b.w;
            acc[3][0] += a.w * b.x; acc[3][1] += a.w * b.y; acc[3][2] += a.w * b.z; acc[3][3] += a.w * b.w;
        }
        __syncthreads();
    }

#pragma unroll
    for (int ii = 0; ii < 4; ii++) {
        float4 o = make_float4(acc[ii][0], acc[ii][1], acc[ii][2], acc[ii][3]);
        *(float4*)(C + (size_t)(bm + ty * 4 + ii) * N + bn + tx * 4) = o;
    }
}

// ---------------------------------------------------------------------------
// RoPE in place. t layout [B*S, nheads*HD]. One thread per (bs, head, d<32) pair.
// ---------------------------------------------------------------------------
__global__ void rope_kernel(float* __restrict__ t,
                            const float* __restrict__ cosb,
                            const float* __restrict__ sinb,
                            int nheads)
{
    int idx = blockIdx.x * blockDim.x + threadIdx.x;
    int total = BB * SS * nheads * (HD / 2);
    if (idx >= total) return;
    int d = idx & 31;
    int rest = idx >> 5;
    int hh = rest % nheads;
    int bs = rest / nheads;
    int s = bs & (SS - 1);

    size_t base = (size_t)bs * nheads * HD + (size_t)hh * HD;
    float c0 = cosb[s * HD + d],      s0 = sinb[s * HD + d];
    float c1 = cosb[s * HD + d + 32], s1 = sinb[s * HD + d + 32];
    float v0 = t[base + d];
    float v1 = t[base + d + 32];
    t[base + d]      = v0 * c0 - v1 * s0;
    t[base + d + 32] = v1 * c1 + v0 * s1;
}

// ---------------------------------------------------------------------------
// Flash attention, causal, GQA (kv head = h/4).
// Block = (q-tile 64 rows, head, batch). 256 threads, 16x16 layout, 4x4 frags.
// Q layout [B*S, NH*HD], K/V layout [B*S, NKH*HD], O layout [B*S, NH*HD].
// ---------------------------------------------------------------------------
__global__ __launch_bounds__(256) void flash_kernel(
    const float* __restrict__ Q, const float* __restrict__ K,
    const float* __restrict__ V, float* __restrict__ O)
{
    __shared__ float Qt[64][64];   // Qt[d][i]
    __shared__ float KP[64][64];   // Kt[d][j], then reused as P[i][j]
    __shared__ float Vs[64][64];   // Vs[j][d]

    const int tid = threadIdx.x;
    const int tx = tid & 15;       // score cols / O dims quad
    const int ty = tid >> 4;       // rows quad
    const int qt = blockIdx.x;
    const int h  = blockIdx.y;
    const int b  = blockIdx.z;
    const int q0 = qt * 64;
    const int kh = h >> 2;

    const float* Qb = Q + (size_t)b * SS * (NH * HD) + (size_t)h * HD;
    const float* Kb = K + (size_t)b * SS * (NKH * HD) + (size_t)kh * HD;
    const float* Vb = V + (size_t)b * SS * (NKH * HD) + (size_t)kh * HD;

    // Load Q tile transposed: Qt[d][i]
    for (int idx = tid; idx < 64 * 16; idx += 256) {
        int i = idx >> 4;
        int c = (idx & 15) << 2;
        float4 v = *(const float4*)(Qb + (size_t)(q0 + i) * (NH * HD) + c);
        Qt[c + 0][i] = v.x;
        Qt[c + 1][i] = v.y;
        Qt[c + 2][i] = v.z;
        Qt[c + 3][i] = v.w;
    }

    float m[4], l[4], acc[4][4];
#pragma unroll
    for (int i = 0; i < 4; i++) {
        m[i] = -1e30f;
        l[i] = 0.0f;
#pragma unroll
        for (int j = 0; j < 4; j++) acc[i][j] = 0.0f;
    }

    for (int kt = 0; kt <= qt; kt++) {
        const int k0 = kt * 64;
        __syncthreads();  // previous iteration finished reading KP (as P) and Vs

        // Load K tile transposed into KP, V tile row-major into Vs
        for (int idx = tid; idx < 64 * 16; idx += 256) {
            int j = idx >> 4;
            int c = (idx & 15) << 2;
            float4 kv = *(const float4*)(Kb + (size_t)(k0 + j) * (NKH * HD) + c);
            KP[c + 0][j] = kv.x;
            KP[c + 1][j] = kv.y;
            KP[c + 2][j] = kv.z;
            KP[c + 3][j] = kv.w;
            float4 vv = *(const float4*)(Vb + (size_t)(k0 + j) * (NKH * HD) + c);
            *(float4*)&Vs[j][c] = vv;
        }
        __syncthreads();

        // S = Q K^T
        float s[4][4];
#pragma unroll
        for (int i = 0; i < 4; i++)
#pragma unroll
            for (int j = 0; j < 4; j++) s[i][j] = 0.0f;

#pragma unroll 8
        for (int d = 0; d < 64; d++) {
            float4 a = *(const float4*)&Qt[d][ty * 4];
            float4 bq = *(const float4*)&KP[d][tx * 4];
            s[0][0] += a.x * bq.x; s[0][1] += a.x * bq.y; s[0][2] += a.x * bq.z; s[0][3] += a.x * bq.w;
            s[1][0] += a.y * bq.x; s[1][1] += a.y * bq.y; s[1][2] += a.y * bq.z; s[1][3] += a.y * bq.w;
            s[2][0] += a.z * bq.x; s[2][1] += a.z * bq.y; s[2][2] += a.z * bq.z; s[2][3] += a.z * bq.w;
            s[3][0] += a.w * bq.x; s[3][1] += a.w * bq.y; s[3][2] += a.w * bq.z; s[3][3] += a.w * bq.w;
        }

        const float sc = 0.125f;  // 1/sqrt(64)
        if (kt == qt) {
#pragma unroll
            for (int ii = 0; ii < 4; ii++) {
                int il = ty * 4 + ii;
#pragma unroll
                for (int jj = 0; jj < 4; jj++) {
                    int jl = tx * 4 + jj;
                    s[ii][jj] = (jl <= il) ? s[ii][jj] * sc : -1e30f;
                }
            }
        } else {
#pragma unroll
            for (int ii = 0; ii < 4; ii++)
#pragma unroll
                for (int jj = 0; jj < 4; jj++) s[ii][jj] *= sc;
        }

        // Online softmax
        float rm[4], rs[4], alpha[4];
#pragma unroll
        for (int ii = 0; ii < 4; ii++) {
            float v = fmaxf(fmaxf(s[ii][0], s[ii][1]), fmaxf(s[ii][2], s[ii][3]));
#pragma unroll
            for (int off = 1; off < 16; off <<= 1)
                v = fmaxf(v, __shfl_xor_sync(0xffffffffu, v, off));
            rm[ii] = v;
        }
#pragma unroll
        for (int ii = 0; ii < 4; ii++) {
            float mn = fmaxf(m[ii], rm[ii]);
            alpha[ii] = __expf(m[ii] - mn);
            m[ii] = mn;
            float sum = 0.0f;
#pragma unroll
            for (int jj = 0; jj < 4; jj++) {
                s[ii][jj] = __expf(s[ii][jj] - mn);
                sum += s[ii][jj];
            }
#pragma unroll
            for (int off = 1; off < 16; off <<= 1)
                sum += __shfl_xor_sync(0xffffffffu, sum, off);
            rs[ii] = sum;
            l[ii] = l[ii] * alpha[ii] + rs[ii];
#pragma unroll
            for (int jj = 0; jj < 4; jj++) acc[ii][jj] *= alpha[ii];
        }

        __syncthreads();  // all threads done reading KP as K^T

        // Store P row-major (conflict-free float4 stores)
#pragma unroll
        for (int ii = 0; ii < 4; ii++) {
            float4 p = make_float4(s[ii][0], s[ii][1], s[ii][2], s[ii][3]);
            *(float4*)&KP[ty * 4 + ii][tx * 4] = p;
        }
        __syncthreads();

        // O += P @ V
#pragma unroll 8
        for (int j = 0; j < 64; j++) {
            float4 vv = *(const float4*)&Vs[j][tx * 4];
            float p0 = KP[ty * 4 + 0][j];
            float p1 = KP[ty * 4 + 1][j];
            float p2 = KP[ty * 4 + 2][j];
            float p3 = KP[ty * 4 + 3][j];
            acc[0][0] += p0 * vv.x; acc[0][1] += p0 * vv.y; acc[0][2] += p0 * vv.z; acc[0][3] += p0 * vv.w;
            acc[1][0] += p1 * vv.x; acc[1][1] += p1 * vv.y; acc[1][2] += p1 * vv.z; acc[1][3] += p1 * vv.w;
            acc[2][0] += p2 * vv.x; acc[2][1] += p2 * vv.y; acc[2][2] += p2 * vv.z; acc[2][3] += p2 * vv.w;
            acc[3][0] += p3 * vv.x; acc[3][1] += p3 * vv.y; acc[3][2] += p3 * vv.z; acc[3][3] += p3 * vv.w;
        }
    }

    // Normalize + write O
#pragma unroll
    for (int ii = 0; ii < 4; ii++) {
        float inv = 1.0f / l[ii];
        float4 o = make_float4(acc[ii][0] * inv, acc[ii][1] * inv,
                               acc[ii][2] * inv, acc[ii][3] * inv);
        *(float4*)(O + (size_t)b * SS * (NH * HD) +
                   (size_t)(q0 + ty * 4 + ii) * (NH * HD) + (size_t)h * HD + tx * 4) = o;
    }
}

// ---------------------------------------------------------------------------
extern "C" void kernel_launch(void* const* d_in, const int* in_sizes, int n_in,
                              void* d_out, int out_size)
{
    const float* x    = (const float*)d_in[0];
    const float* cosb = (const float*)d_in[1];
    const float* sinb = (const float*)d_in[2];
    const float* wq   = (const float*)d_in[3];
    const float* wk   = (const float*)d_in[4];
    const float* wv   = (const float*)d_in[5];
    const float* wo   = (const float*)d_in[6];
    float* out = (float*)d_out;

    float *qp, *kp, *vp, *op;
    cudaGetSymbolAddress((void**)&qp, g_q);
    cudaGetSymbolAddress((void**)&kp, g_k);
    cudaGetSymbolAddress((void**)&vp, g_v);
    cudaGetSymbolAddress((void**)&op, g_o);

    const int M = BB * SS;  // 4096

    // QKV projections
    sgemm_kernel<<<dim3((NH * HD) / 64, M / 64), 256>>>(x, wq, qp, M, NH * HD, DMODEL);
    sgemm_kernel<<<dim3((NKH * HD) / 64, M / 64), 256>>>(x, wk, kp, M, NKH * HD, DMODEL);
    sgemm_kernel<<<dim3((NKH * HD) / 64, M / 64), 256>>>(x, wv, vp, M, NKH * HD, DMODEL);

    // RoPE on q and k
    {
        int nq = BB * SS * NH * (HD / 2);
        rope_kernel<<<(nq + 255) / 256, 256>>>(qp, cosb, sinb, NH);
        int nk = BB * SS * NKH * (HD / 2);
        rope_kernel<<<(nk + 255) / 256, 256>>>(kp, cosb, sinb, NKH);
    }

    // Causal GQA flash attention
    flash_kernel<<<dim3(SS / 64, NH, BB), 256>>>(qp, kp, vp, op);

    // Output projection
    sgemm_kernel<<<dim3(DMODEL / 64, M / 64), 256>>>(op, wo, out, M, DMODEL, DMODEL);
}

// round 3
// speedup vs baseline: 1.2886x; 1.2886x over previous
#include <cuda_runtime.h>
#include <cuda_bf16.h>
#include <cstdint>
#include <math.h>

#define BB 2
#define SS 2048
#define DMODEL 1024
#define NH 16
#define NKH 4
#define HD 64

// ---------------------------------------------------------------------------
// Scratch (device globals: allocation-free)
// ---------------------------------------------------------------------------
__device__ float g_q[BB * SS * NH * HD];
__device__ float g_k[BB * SS * NKH * HD];
__device__ float g_v[BB * SS * NKH * HD];
__device__ float g_o[BB * SS * NH * HD];

__device__ __nv_bfloat16 g_xh[BB * SS * DMODEL];
__device__ __nv_bfloat16 g_xl[BB * SS * DMODEL];
__device__ __nv_bfloat16 g_oh[BB * SS * NH * HD];
__device__ __nv_bfloat16 g_ol[BB * SS * NH * HD];
__device__ __nv_bfloat16 g_wqh[(NH * HD) * DMODEL];
__device__ __nv_bfloat16 g_wql[(NH * HD) * DMODEL];
__device__ __nv_bfloat16 g_wkh[(NKH * HD) * DMODEL];
__device__ __nv_bfloat16 g_wkl[(NKH * HD) * DMODEL];
__device__ __nv_bfloat16 g_wvh[(NKH * HD) * DMODEL];
__device__ __nv_bfloat16 g_wvl[(NKH * HD) * DMODEL];
__device__ __nv_bfloat16 g_woh[DMODEL * (NH * HD)];
__device__ __nv_bfloat16 g_wol[DMODEL * (NH * HD)];

// ---------------------------------------------------------------------------
// Warp-level MMA helpers (non-'a' features: legal on compute_103)
// ---------------------------------------------------------------------------
__device__ __forceinline__ uint32_t smem_u32(const void* p) {
    uint32_t a;
    asm("{ .reg .u64 t; cvta.to.shared.u64 t, %1; cvt.u32.u64 %0, t; }"
        : "=r"(a) : "l"(p));
    return a;
}

__device__ __forceinline__ void ldsm4(uint32_t& r0, uint32_t& r1,
                                      uint32_t& r2, uint32_t& r3, uint32_t a) {
    asm volatile("ldmatrix.sync.aligned.m8n8.x4.shared.b16 {%0,%1,%2,%3}, [%4];"
                 : "=r"(r0), "=r"(r1), "=r"(r2), "=r"(r3) : "r"(a));
}

__device__ __forceinline__ void ldsm2(uint32_t& r0, uint32_t& r1, uint32_t a) {
    asm volatile("ldmatrix.sync.aligned.m8n8.x2.shared.b16 {%0,%1}, [%2];"
                 : "=r"(r0), "=r"(r1) : "r"(a));
}

__device__ __forceinline__ void mma_bf16(float* c, const uint32_t* a,
                                         const uint32_t* b) {
    asm volatile(
        "mma.sync.aligned.m16n8k16.row.col.f32.bf16.bf16.f32 "
        "{%0,%1,%2,%3}, {%4,%5,%6,%7}, {%8,%9}, {%0,%1,%2,%3};"
        : "+f"(c[0]), "+f"(c[1]), "+f"(c[2]), "+f"(c[3])
        : "r"(a[0]), "r"(a[1]), "r"(a[2]), "r"(a[3]), "r"(b[0]), "r"(b[1]));
}

#define CP_ASYNC16(sa, ga) \
    asm volatile("cp.async.cg.shared.global [%0], [%1], 16;" \
                 :: "r"(sa), "l"(ga))
#define CP_COMMIT() asm volatile("cp.async.commit_group;")
#define CP_WAIT(N)  asm volatile("cp.async.wait_group %0;" :: "n"(N))

// ---------------------------------------------------------------------------
// bf16x3 HMMA GEMM: C[M,N] = A[M,K] @ B[N,K]^T, fp32 out.
// 128x128 CTA tile, BK=32, 8 warps (2x4), warp tile 64x32, cp.async 2-stage.
// smem row stride = 40 bf16 (80B): conflict-free ldmatrix, 16B-aligned.
// ---------------------------------------------------------------------------
#define BK 32
#define GSTRIDE 40
#define GTILE_B (128 * GSTRIDE * 2)            // 10240 bytes per tile
#define GOFF(t, st) (((st) * 4 + (t)) * GTILE_B)
#define GEMM_SMEM (8 * GTILE_B)                // 81920 bytes

__global__ __launch_bounds__(256) void gemm_bf16x3_kernel(
    const __nv_bfloat16* __restrict__ Ah, const __nv_bfloat16* __restrict__ Al,
    const __nv_bfloat16* __restrict__ Bh, const __nv_bfloat16* __restrict__ Bl,
    float* __restrict__ C, int M, int N, int K)
{
    extern __shared__ __align__(128) char smem[];
    const uint32_t sb = smem_u32(smem);
    const int tid = threadIdx.x;
    const int wid = tid >> 5;
    const int lane = tid & 31;
    const int bm = blockIdx.y * 128;
    const int bn = blockIdx.x * 128;
    const int warp_m = (wid >> 2) * 64;   // 0 or 64
    const int warp_n = (wid & 3) * 32;    // 0,32,64,96

    const __nv_bfloat16* gp[4] = {
        Ah + (size_t)bm * K, Al + (size_t)bm * K,
        Bh + (size_t)bn * K, Bl + (size_t)bn * K };

    // loader indices: 512 x 16B per tile, 256 threads -> 2 iters
    const int lrow0 = tid >> 2;            // 0..63
    const int lq = tid & 3;                // 16B chunk within 32-col row

    auto load_stage = [&](int c, int st) {
#pragma unroll
        for (int t = 0; t < 4; t++) {
            const __nv_bfloat16* P = gp[t] + (size_t)c * BK;
#pragma unroll
            for (int it = 0; it < 2; it++) {
                int row = lrow0 + it * 64;
                uint32_t sa = sb + GOFF(t, st) + (row * GSTRIDE + lq * 8) * 2;
                CP_ASYNC16(sa, P + (size_t)row * K + lq * 8);
            }
        }
        CP_COMMIT();
    };

    float acc[4][4][4];
#pragma unroll
    for (int i = 0; i < 4; i++)
#pragma unroll
        for (int j = 0; j < 4; j++)
#pragma unroll
            for (int r = 0; r < 4; r++) acc[i][j][r] = 0.0f;

    const int nchunk = K / BK;
    load_stage(0, 0);

    // fragment smem address bases (element offsets computed per use)
    const int a_r = lane & 15;             // ldmatrix.x4 row
    const int a_c = (lane >> 4) * 8;       // ldmatrix.x4 col group
    const int b_r = lane & 7;              // ldmatrix.x2 row (lanes 0-15 used)
    const int b_c = ((lane >> 3) & 1) * 8;

    for (int c = 0; c < nchunk; c++) {
        const int st = c & 1;
        if (c + 1 < nchunk) {
            load_stage(c + 1, st ^ 1);
            CP_WAIT(1);
        } else {
            CP_WAIT(0);
        }
        __syncthreads();

        const uint32_t sAh = sb + GOFF(0, st);
        const uint32_t sAl = sb + GOFF(1, st);
        const uint32_t sBh = sb + GOFF(2, st);
        const uint32_t sBl = sb + GOFF(3, st);

#pragma unroll
        for (int kf = 0; kf < 2; kf++) {
            const int kc = kf * 16;
            uint32_t ah[4][4], al[4][4], bh[4][2], bl[4][2];
#pragma unroll
            for (int mf = 0; mf < 4; mf++) {
                uint32_t ad = ((warp_m + mf * 16 + a_r) * GSTRIDE + kc + a_c) * 2;
                ldsm4(ah[mf][0], ah[mf][1], ah[mf][2], ah[mf][3], sAh + ad);
            }
#pragma unroll
            for (int nf = 0; nf < 4; nf++) {
                uint32_t bd = ((warp_n + nf * 8 + b_r) * GSTRIDE + kc + b_c) * 2;
                ldsm2(bh[nf][0], bh[nf][1], sBh + bd);
            }
#pragma unroll
            for (int mf = 0; mf < 4; mf++)
#pragma unroll
                for (int nf = 0; nf < 4; nf++)
                    mma_bf16(acc[mf][nf], ah[mf], bh[nf]);

#pragma unroll
            for (int nf = 0; nf < 4; nf++) {
                uint32_t bd = ((warp_n + nf * 8 + b_r) * GSTRIDE + kc + b_c) * 2;
                ldsm2(bl[nf][0], bl[nf][1], sBl + bd);
            }
#pragma unroll
            for (int mf = 0; mf < 4; mf++)
#pragma unroll
                for (int nf = 0; nf < 4; nf++)
                    mma_bf16(acc[mf][nf], ah[mf], bl[nf]);

#pragma unroll
            for (int mf = 0; mf < 4; mf++) {
                uint32_t ad = ((warp_m + mf * 16 + a_r) * GSTRIDE + kc + a_c) * 2;
                ldsm4(al[mf][0], al[mf][1], al[mf][2], al[mf][3], sAl + ad);
            }
#pragma unroll
            for (int mf = 0; mf < 4; mf++)
#pragma unroll
                for (int nf = 0; nf < 4; nf++)
                    mma_bf16(acc[mf][nf], al[mf], bh[nf]);
        }
        __syncthreads();
    }

    // epilogue: fragment (row = lane/4 [+8], col = (lane%4)*2)
    const int er = lane >> 2;
    const int ec = (lane & 3) * 2;
#pragma unroll
    for (int mf = 0; mf < 4; mf++) {
#pragma unroll
        for (int nf = 0; nf < 4; nf++) {
            float* base = C + (size_t)(bm + warp_m + mf * 16 + er) * N
                            + bn + warp_n + nf * 8 + ec;
            *(float2*)base = make_float2(acc[mf][nf][0], acc[mf][nf][1]);
            *(float2*)(base + 8 * N) = make_float2(acc[mf][nf][2], acc[mf][nf][3]);
        }
    }
}

// ---------------------------------------------------------------------------
// Elementwise split fp32 -> (hi, lo) bf16.
// ---------------------------------------------------------------------------
__global__ void split_kernel(const float4* __restrict__ src,
                             __nv_bfloat162* __restrict__ dh,
                             __nv_bfloat162* __restrict__ dl, int n4)
{
    int i = blockIdx.x * blockDim.x + threadIdx.x;
    if (i >= n4) return;
    float4 v = src[i];
    __nv_bfloat16 h0 = __float2bfloat16(v.x);
    __nv_bfloat16 h1 = __float2bfloat16(v.y);
    __nv_bfloat16 h2 = __float2bfloat16(v.z);
    __nv_bfloat16 h3 = __float2bfloat16(v.w);
    dh[2 * i]     = __nv_bfloat162(h0, h1);
    dh[2 * i + 1] = __nv_bfloat162(h2, h3);
    __nv_bfloat16 l0 = __float2bfloat16(v.x - __bfloat162float(h0));
    __nv_bfloat16 l1 = __float2bfloat16(v.y - __bfloat162float(h1));
    __nv_bfloat16 l2 = __float2bfloat16(v.z - __bfloat162float(h2));
    __nv_bfloat16 l3 = __float2bfloat16(v.w - __bfloat162float(h3));
    dl[2 * i]     = __nv_bfloat162(l0, l1);
    dl[2 * i + 1] = __nv_bfloat162(l2, l3);
}

// ---------------------------------------------------------------------------
// Transpose + split: src [K][N] fp32 -> dst_hi/lo [N][K] bf16.
// ---------------------------------------------------------------------------
__global__ void transpose_split_kernel(const float* __restrict__ src,
                                       __nv_bfloat16* __restrict__ dh,
                                       __nv_bfloat16* __restrict__ dl,
                                       int K, int N)
{
    __shared__ float t[32][33];
    const int k0 = blockIdx.y * 32, n0 = blockIdx.x * 32;
    const int tx = threadIdx.x, ty = threadIdx.y;  // 32 x 8
#pragma unroll
    for (int i = 0; i < 32; i += 8)
        t[ty + i][tx] = src[(size_t)(k0 + ty + i) * N + n0 + tx];
    __syncthreads();
#pragma unroll
    for (int i = 0; i < 32; i += 8) {
        float v = t[tx][ty + i];
        __nv_bfloat16 h = __float2bfloat16(v);
        float rres = v - __bfloat162float(h);
        size_t o = (size_t)(n0 + ty + i) * K + k0 + tx;
        dh[o] = h;
        dl[o] = __float2bfloat16(rres);
    }
}

// ---------------------------------------------------------------------------
// RoPE in place. t layout [B*S, nheads*HD].
// ---------------------------------------------------------------------------
__global__ void rope_kernel(float* __restrict__ t,
                            const float* __restrict__ cosb,
                            const float* __restrict__ sinb,
                            int nheads)
{
    int idx = blockIdx.x * blockDim.x + threadIdx.x;
    int total = BB * SS * nheads * (HD / 2);
    if (idx >= total) return;
    int d = idx & 31;
    int rest = idx >> 5;
    int hh = rest % nheads;
    int bs = rest / nheads;
    int s = bs & (SS - 1);

    size_t base = (size_t)bs * nheads * HD + (size_t)hh * HD;
    float c0 = cosb[s * HD + d],      s0 = sinb[s * HD + d];
    float c1 = cosb[s * HD + d + 32], s1 = sinb[s * HD + d + 32];
    float v0 = t[base + d];
    float v1 = t[base + d + 32];
    t[base + d]      = v0 * c0 - v1 * s0;
    t[base + d + 32] = v1 * c1 + v0 * s1;
}

// ---------------------------------------------------------------------------
// Flash attention (fp32 CUDA-core), causal, GQA. Unchanged (passing).
// ---------------------------------------------------------------------------
__global__ __launch_bounds__(256) void flash_kernel(
    const float* __restrict__ Q, const float* __restrict__ K,
    const float* __restrict__ V, float* __restrict__ O)
{
    __shared__ float Qt[64][64];
    __shared__ float KP[64][64];
    __shared__ float Vs[64][64];

    const int tid = threadIdx.x;
    const int tx = tid & 15;
    const int ty = tid >> 4;
    const int qt = blockIdx.x;
    const int h  = blockIdx.y;
    const int b  = blockIdx.z;
    const int q0 = qt * 64;
    const int kh = h >> 2;

    const float* Qb = Q + (size_t)b * SS * (NH * HD) + (size_t)h * HD;
    const float* Kb = K + (size_t)b * SS * (NKH * HD) + (size_t)kh * HD;
    const float* Vb = V + (size_t)b * SS * (NKH * HD) + (size_t)kh * HD;

    for (int idx = tid; idx < 64 * 16; idx += 256) {
        int i = idx >> 4;
        int c = (idx & 15) << 2;
        float4 v = *(const float4*)(Qb + (size_t)(q0 + i) * (NH * HD) + c);
        Qt[c + 0][i] = v.x;
        Qt[c + 1][i] = v.y;
        Qt[c + 2][i] = v.z;
        Qt[c + 3][i] = v.w;
    }

    float m[4], l[4], acc[4][4];
#pragma unroll
    for (int i = 0; i < 4; i++) {
        m[i] = -1e30f;
        l[i] = 0.0f;
#pragma unroll
        for (int j = 0; j < 4; j++) acc[i][j] = 0.0f;
    }

    for (int kt = 0; kt <= qt; kt++) {
        const int k0 = kt * 64;
        __syncthreads();

        for (int idx = tid; idx < 64 * 16; idx += 256) {
            int j = idx >> 4;
            int c = (idx & 15) << 2;
            float4 kv = *(const float4*)(Kb + (size_t)(k0 + j) * (NKH * HD) + c);
            KP[c + 0][j] = kv.x;
            KP[c + 1][j] = kv.y;
            KP[c + 2][j] = kv.z;
            KP[c + 3][j] = kv.w;
            float4 vv = *(const float4*)(Vb + (size_t)(k0 + j) * (NKH * HD) + c);
            *(float4*)&Vs[j][c] = vv;
        }
        __syncthreads();

        float s[4][4];
#pragma unroll
        for (int i = 0; i < 4; i++)
#pragma unroll
            for (int j = 0; j < 4; j++) s[i][j] = 0.0f;

#pragma unroll 8
        for (int d = 0; d < 64; d++) {
            float4 a = *(const float4*)&Qt[d][ty * 4];
            float4 bq = *(const float4*)&KP[d][tx * 4];
            s[0][0] += a.x * bq.x; s[0][1] += a.x * bq.y; s[0][2] += a.x * bq.z; s[0][3] += a.x * bq.w;
            s[1][0] += a.y * bq.x; s[1][1] += a.y * bq.y; s[1][2] += a.y * bq.z; s[1][3] += a.y * bq.w;
            s[2][0] += a.z * bq.x; s[2][1] += a.z * bq.y; s[2][2] += a.z * bq.z; s[2][3] += a.z * bq.w;
            s[3][0] += a.w * bq.x; s[3][1] += a.w * bq.y; s[3][2] += a.w * bq.z; s[3][3] += a.w * bq.w;
        }

        const float sc = 0.125f;
        if (kt == qt) {
#pragma unroll
            for (int ii = 0; ii < 4; ii++) {
                int il = ty * 4 + ii;
#pragma unroll
                for (int jj = 0; jj < 4; jj++) {
                    int jl = tx * 4 + jj;
                    s[ii][jj] = (jl <= il) ? s[ii][jj] * sc : -1e30f;
                }
            }
        } else {
#pragma unroll
            for (int ii = 0; ii < 4; ii++)
#pragma unroll
                for (int jj = 0; jj < 4; jj++) s[ii][jj] *= sc;
        }

        float rm[4], rs[4], alpha[4];
#pragma unroll
        for (int ii = 0; ii < 4; ii++) {
            float v = fmaxf(fmaxf(s[ii][0], s[ii][1]), fmaxf(s[ii][2], s[ii][3]));
#pragma unroll
            for (int off = 1; off < 16; off <<= 1)
                v = fmaxf(v, __shfl_xor_sync(0xffffffffu, v, off));
            rm[ii] = v;
        }
#pragma unroll
        for (int ii = 0; ii < 4; ii++) {
            float mn = fmaxf(m[ii], rm[ii]);
            alpha[ii] = __expf(m[ii] - mn);
            m[ii] = mn;
            float sum = 0.0f;
#pragma unroll
            for (int jj = 0; jj < 4; jj++) {
                s[ii][jj] = __expf(s[ii][jj] - mn);
                sum += s[ii][jj];
            }
#pragma unroll
            for (int off = 1; off < 16; off <<= 1)
                sum += __shfl_xor_sync(0xffffffffu, sum, off);
            rs[ii] = sum;
            l[ii] = l[ii] * alpha[ii] + rs[ii];
#pragma unroll
            for (int jj = 0; jj < 4; jj++) acc[ii][jj] *= alpha[ii];
        }

        __syncthreads();

#pragma unroll
        for (int ii = 0; ii < 4; ii++) {
            float4 p = make_float4(s[ii][0], s[ii][1], s[ii][2], s[ii][3]);
            *(float4*)&KP[ty * 4 + ii][tx * 4] = p;
        }
        __syncthreads();

#pragma unroll 8
        for (int j = 0; j < 64; j++) {
            float4 vv = *(const float4*)&Vs[j][tx * 4];
            float p0 = KP[ty * 4 + 0][j];
            float p1 = KP[ty * 4 + 1][j];
            float p2 = KP[ty * 4 + 2][j];
            float p3 = KP[ty * 4 + 3][j];
            acc[0][0] += p0 * vv.x; acc[0][1] += p0 * vv.y; acc[0][2] += p0 * vv.z; acc[0][3] += p0 * vv.w;
            acc[1][0] += p1 * vv.x; acc[1][1] += p1 * vv.y; acc[1][2] += p1 * vv.z; acc[1][3] += p1 * vv.w;
            acc[2][0] += p2 * vv.x; acc[2][1] += p2 * vv.y; acc[2][2] += p2 * vv.z; acc[2][3] += p2 * vv.w;
            acc[3][0] += p3 * vv.x; acc[3][1] += p3 * vv.y; acc[3][2] += p3 * vv.z; acc[3][3] += p3 * vv.w;
        }
    }

#pragma unroll
    for (int ii = 0; ii < 4; ii++) {
        float inv = 1.0f / l[ii];
        float4 o = make_float4(acc[ii][0] * inv, acc[ii][1] * inv,
                               acc[ii][2] * inv, acc[ii][3] * inv);
        *(float4*)(O + (size_t)b * SS * (NH * HD) +
                   (size_t)(q0 + ty * 4 + ii) * (NH * HD) + (size_t)h * HD + tx * 4) = o;
    }
}

// ---------------------------------------------------------------------------
extern "C" void kernel_launch(void* const* d_in, const int* in_sizes, int n_in,
                              void* d_out, int out_size)
{
    const float* x    = (const float*)d_in[0];
    const float* cosb = (const float*)d_in[1];
    const float* sinb = (const float*)d_in[2];
    const float* wq   = (const float*)d_in[3];
    const float* wk   = (const float*)d_in[4];
    const float* wv   = (const float*)d_in[5];
    const float* wo   = (const float*)d_in[6];
    float* out = (float*)d_out;

    float *qp, *kp, *vp, *op;
    cudaGetSymbolAddress((void**)&qp, g_q);
    cudaGetSymbolAddress((void**)&kp, g_k);
    cudaGetSymbolAddress((void**)&vp, g_v);
    cudaGetSymbolAddress((void**)&op, g_o);

    __nv_bfloat16 *xh, *xl, *oh, *ol;
    __nv_bfloat16 *wqh, *wql, *wkh, *wkl, *wvh, *wvl, *woh, *wol;
    cudaGetSymbolAddress((void**)&xh, g_xh);
    cudaGetSymbolAddress((void**)&xl, g_xl);
    cudaGetSymbolAddress((void**)&oh, g_oh);
    cudaGetSymbolAddress((void**)&ol, g_ol);
    cudaGetSymbolAddress((void**)&wqh, g_wqh);
    cudaGetSymbolAddress((void**)&wql, g_wql);
    cudaGetSymbolAddress((void**)&wkh, g_wkh);
    cudaGetSymbolAddress((void**)&wkl, g_wkl);
    cudaGetSymbolAddress((void**)&wvh, g_wvh);
    cudaGetSymbolAddress((void**)&wvl, g_wvl);
    cudaGetSymbolAddress((void**)&woh, g_woh);
    cudaGetSymbolAddress((void**)&wol, g_wol);

    cudaFuncSetAttribute(gemm_bf16x3_kernel,
                         cudaFuncAttributeMaxDynamicSharedMemorySize, GEMM_SMEM);

    const int M = BB * SS;  // 4096

    // Split activations, transpose+split weights
    {
        int n4 = M * DMODEL / 4;
        split_kernel<<<(n4 + 255) / 256, 256>>>(
            (const float4*)x, (__nv_bfloat162*)xh, (__nv_bfloat162*)xl, n4);
        dim3 blk(32, 8);
        transpose_split_kernel<<<dim3((NH * HD) / 32, DMODEL / 32), blk>>>(wq, wqh, wql, DMODEL, NH * HD);
        transpose_split_kernel<<<dim3((NKH * HD) / 32, DMODEL / 32), blk>>>(wk, wkh, wkl, DMODEL, NKH * HD);
        transpose_split_kernel<<<dim3((NKH * HD) / 32, DMODEL / 32), blk>>>(wv, wvh, wvl, DMODEL, NKH * HD);
        transpose_split_kernel<<<dim3(DMODEL / 32, (NH * HD) / 32), blk>>>(wo, woh, wol, NH * HD, DMODEL);
    }

    // QKV projections (HMMA bf16x3)
    gemm_bf16x3_kernel<<<dim3((NH * HD) / 128, M / 128), 256, GEMM_SMEM>>>(
        xh, xl, wqh, wql, qp, M, NH * HD, DMODEL);
    gemm_bf16x3_kernel<<<dim3((NKH * HD) / 128, M / 128), 256, GEMM_SMEM>>>(
        xh, xl, wkh, wkl, kp, M, NKH * HD, DMODEL);
    gemm_bf16x3_kernel<<<dim3((NKH * HD) / 128, M / 128), 256, GEMM_SMEM>>>(
        xh, xl, wvh, wvl, vp, M, NKH * HD, DMODEL);

    // RoPE on q and k
    {
        int nq = BB * SS * NH * (HD / 2);
        rope_kernel<<<(nq + 255) / 256, 256>>>(qp, cosb, sinb, NH);
        int nk = BB * SS * NKH * (HD / 2);
        rope_kernel<<<(nk + 255) / 256, 256>>>(kp, cosb, sinb, NKH);
    }

    // Causal GQA flash attention (fp32)
    flash_kernel<<<dim3(SS / 64, NH, BB), 256>>>(qp, kp, vp, op);

    // Split attention output, then output projection (HMMA bf16x3)
    {
        int n4 = M * (NH * HD) / 4;
        split_kernel<<<(n4 + 255) / 256, 256>>>(
            (const float4*)op, (__nv_bfloat162*)oh, (__nv_bfloat162*)ol, n4);
    }
    gemm_bf16x3_kernel<<<dim3(DMODEL / 128, M / 128), 256, GEMM_SMEM>>>(
        oh, ol, woh, wol, out, M, DMODEL, DMODEL);
}

// round 4
// speedup vs baseline: 1.7312x; 1.3435x over previous
#include <cuda_runtime.h>
#include <cuda_bf16.h>
#include <cstdint>
#include <math.h>

#define BB 2
#define SS 2048
#define DMODEL 1024
#define NH 16
#define NKH 4
#define HD 64

// ---------------------------------------------------------------------------
// Scratch (device globals: allocation-free)
// ---------------------------------------------------------------------------
__device__ float g_q[BB * SS * NH * HD];
__device__ float g_k[BB * SS * NKH * HD];
__device__ float g_v[BB * SS * NKH * HD];
__device__ float g_o[BB * SS * NH * HD];

__device__ __nv_bfloat16 g_xh[BB * SS * DMODEL];
__device__ __nv_bfloat16 g_xl[BB * SS * DMODEL];
__device__ __nv_bfloat16 g_oh[BB * SS * NH * HD];
__device__ __nv_bfloat16 g_ol[BB * SS * NH * HD];
__device__ __nv_bfloat16 g_wqh[(NH * HD) * DMODEL];
__device__ __nv_bfloat16 g_wql[(NH * HD) * DMODEL];
__device__ __nv_bfloat16 g_wkh[(NKH * HD) * DMODEL];
__device__ __nv_bfloat16 g_wkl[(NKH * HD) * DMODEL];
__device__ __nv_bfloat16 g_wvh[(NKH * HD) * DMODEL];
__device__ __nv_bfloat16 g_wvl[(NKH * HD) * DMODEL];
__device__ __nv_bfloat16 g_woh[DMODEL * (NH * HD)];
__device__ __nv_bfloat16 g_wol[DMODEL * (NH * HD)];

// flash attention operands (bf16 split)
__device__ __nv_bfloat16 g_qh[BB * SS * NH * HD];
__device__ __nv_bfloat16 g_ql[BB * SS * NH * HD];
__device__ __nv_bfloat16 g_kh2[BB * SS * NKH * HD];
__device__ __nv_bfloat16 g_kl2[BB * SS * NKH * HD];
__device__ __nv_bfloat16 g_vth[BB * NKH * HD * SS];   // [b][kh][d][s]
__device__ __nv_bfloat16 g_vtl[BB * NKH * HD * SS];

// ---------------------------------------------------------------------------
// Warp-level MMA helpers (non-'a' features: legal on compute_103)
// ---------------------------------------------------------------------------
__device__ __forceinline__ uint32_t smem_u32(const void* p) {
    uint32_t a;
    asm("{ .reg .u64 t; cvta.to.shared.u64 t, %1; cvt.u32.u64 %0, t; }"
        : "=r"(a) : "l"(p));
    return a;
}

__device__ __forceinline__ void ldsm4(uint32_t& r0, uint32_t& r1,
                                      uint32_t& r2, uint32_t& r3, uint32_t a) {
    asm volatile("ldmatrix.sync.aligned.m8n8.x4.shared.b16 {%0,%1,%2,%3}, [%4];"
                 : "=r"(r0), "=r"(r1), "=r"(r2), "=r"(r3) : "r"(a));
}

__device__ __forceinline__ void ldsm2(uint32_t& r0, uint32_t& r1, uint32_t a) {
    asm volatile("ldmatrix.sync.aligned.m8n8.x2.shared.b16 {%0,%1}, [%2];"
                 : "=r"(r0), "=r"(r1) : "r"(a));
}

__device__ __forceinline__ void mma_bf16(float* c, const uint32_t* a,
                                         const uint32_t* b) {
    asm volatile(
        "mma.sync.aligned.m16n8k16.row.col.f32.bf16.bf16.f32 "
        "{%0,%1,%2,%3}, {%4,%5,%6,%7}, {%8,%9}, {%0,%1,%2,%3};"
        : "+f"(c[0]), "+f"(c[1]), "+f"(c[2]), "+f"(c[3])
        : "r"(a[0]), "r"(a[1]), "r"(a[2]), "r"(a[3]), "r"(b[0]), "r"(b[1]));
}

#define CP_ASYNC16(sa, ga) \
    asm volatile("cp.async.cg.shared.global [%0], [%1], 16;" \
                 :: "r"(sa), "l"(ga))
#define CP_COMMIT() asm volatile("cp.async.commit_group;")
#define CP_WAIT(N)  asm volatile("cp.async.wait_group %0;" :: "n"(N))

// ---------------------------------------------------------------------------
// bf16x3 HMMA GEMM (unchanged from R3)
// ---------------------------------------------------------------------------
#define BK 32
#define GSTRIDE 40
#define GTILE_B (128 * GSTRIDE * 2)
#define GOFF(t, st) (((st) * 4 + (t)) * GTILE_B)
#define GEMM_SMEM (8 * GTILE_B)

__global__ __launch_bounds__(256) void gemm_bf16x3_kernel(
    const __nv_bfloat16* __restrict__ Ah, const __nv_bfloat16* __restrict__ Al,
    const __nv_bfloat16* __restrict__ Bh, const __nv_bfloat16* __restrict__ Bl,
    float* __restrict__ C, int M, int N, int K)
{
    extern __shared__ __align__(128) char smem[];
    const uint32_t sb = smem_u32(smem);
    const int tid = threadIdx.x;
    const int wid = tid >> 5;
    const int lane = tid & 31;
    const int bm = blockIdx.y * 128;
    const int bn = blockIdx.x * 128;
    const int warp_m = (wid >> 2) * 64;
    const int warp_n = (wid & 3) * 32;

    const __nv_bfloat16* gp[4] = {
        Ah + (size_t)bm * K, Al + (size_t)bm * K,
        Bh + (size_t)bn * K, Bl + (size_t)bn * K };

    const int lrow0 = tid >> 2;
    const int lq = tid & 3;

    auto load_stage = [&](int c, int st) {
#pragma unroll
        for (int t = 0; t < 4; t++) {
            const __nv_bfloat16* P = gp[t] + (size_t)c * BK;
#pragma unroll
            for (int it = 0; it < 2; it++) {
                int row = lrow0 + it * 64;
                uint32_t sa = sb + GOFF(t, st) + (row * GSTRIDE + lq * 8) * 2;
                CP_ASYNC16(sa, P + (size_t)row * K + lq * 8);
            }
        }
        CP_COMMIT();
    };

    float acc[4][4][4];
#pragma unroll
    for (int i = 0; i < 4; i++)
#pragma unroll
        for (int j = 0; j < 4; j++)
#pragma unroll
            for (int r = 0; r < 4; r++) acc[i][j][r] = 0.0f;

    const int nchunk = K / BK;
    load_stage(0, 0);

    const int a_r = lane & 15;
    const int a_c = (lane >> 4) * 8;
    const int b_r = lane & 7;
    const int b_c = ((lane >> 3) & 1) * 8;

    for (int c = 0; c < nchunk; c++) {
        const int st = c & 1;
        if (c + 1 < nchunk) {
            load_stage(c + 1, st ^ 1);
            CP_WAIT(1);
        } else {
            CP_WAIT(0);
        }
        __syncthreads();

        const uint32_t sAh = sb + GOFF(0, st);
        const uint32_t sAl = sb + GOFF(1, st);
        const uint32_t sBh = sb + GOFF(2, st);
        const uint32_t sBl = sb + GOFF(3, st);

#pragma unroll
        for (int kf = 0; kf < 2; kf++) {
            const int kc = kf * 16;
            uint32_t ah[4][4], al[4][4], bh[4][2], bl[4][2];
#pragma unroll
            for (int mf = 0; mf < 4; mf++) {
                uint32_t ad = ((warp_m + mf * 16 + a_r) * GSTRIDE + kc + a_c) * 2;
                ldsm4(ah[mf][0], ah[mf][1], ah[mf][2], ah[mf][3], sAh + ad);
            }
#pragma unroll
            for (int nf = 0; nf < 4; nf++) {
                uint32_t bd = ((warp_n + nf * 8 + b_r) * GSTRIDE + kc + b_c) * 2;
                ldsm2(bh[nf][0], bh[nf][1], sBh + bd);
            }
#pragma unroll
            for (int mf = 0; mf < 4; mf++)
#pragma unroll
                for (int nf = 0; nf < 4; nf++)
                    mma_bf16(acc[mf][nf], ah[mf], bh[nf]);

#pragma unroll
            for (int nf = 0; nf < 4; nf++) {
                uint32_t bd = ((warp_n + nf * 8 + b_r) * GSTRIDE + kc + b_c) * 2;
                ldsm2(bl[nf][0], bl[nf][1], sBl + bd);
            }
#pragma unroll
            for (int mf = 0; mf < 4; mf++)
#pragma unroll
                for (int nf = 0; nf < 4; nf++)
                    mma_bf16(acc[mf][nf], ah[mf], bl[nf]);

#pragma unroll
            for (int mf = 0; mf < 4; mf++) {
                uint32_t ad = ((warp_m + mf * 16 + a_r) * GSTRIDE + kc + a_c) * 2;
                ldsm4(al[mf][0], al[mf][1], al[mf][2], al[mf][3], sAl + ad);
            }
#pragma unroll
            for (int mf = 0; mf < 4; mf++)
#pragma unroll
                for (int nf = 0; nf < 4; nf++)
                    mma_bf16(acc[mf][nf], al[mf], bh[nf]);
        }
        __syncthreads();
    }

    const int er = lane >> 2;
    const int ec = (lane & 3) * 2;
#pragma unroll
    for (int mf = 0; mf < 4; mf++) {
#pragma unroll
        for (int nf = 0; nf < 4; nf++) {
            float* base = C + (size_t)(bm + warp_m + mf * 16 + er) * N
                            + bn + warp_n + nf * 8 + ec;
            *(float2*)base = make_float2(acc[mf][nf][0], acc[mf][nf][1]);
            *(float2*)(base + 8 * N) = make_float2(acc[mf][nf][2], acc[mf][nf][3]);
        }
    }
}

// ---------------------------------------------------------------------------
// Elementwise split fp32 -> (hi, lo) bf16.
// ---------------------------------------------------------------------------
__global__ void split_kernel(const float4* __restrict__ src,
                             __nv_bfloat162* __restrict__ dh,
                             __nv_bfloat162* __restrict__ dl, int n4)
{
    int i = blockIdx.x * blockDim.x + threadIdx.x;
    if (i >= n4) return;
    float4 v = src[i];
    __nv_bfloat16 h0 = __float2bfloat16(v.x);
    __nv_bfloat16 h1 = __float2bfloat16(v.y);
    __nv_bfloat16 h2 = __float2bfloat16(v.z);
    __nv_bfloat16 h3 = __float2bfloat16(v.w);
    dh[2 * i]     = __nv_bfloat162(h0, h1);
    dh[2 * i + 1] = __nv_bfloat162(h2, h3);
    __nv_bfloat16 l0 = __float2bfloat16(v.x - __bfloat162float(h0));
    __nv_bfloat16 l1 = __float2bfloat16(v.y - __bfloat162float(h1));
    __nv_bfloat16 l2 = __float2bfloat16(v.z - __bfloat162float(h2));
    __nv_bfloat16 l3 = __float2bfloat16(v.w - __bfloat162float(h3));
    dl[2 * i]     = __nv_bfloat162(l0, l1);
    dl[2 * i + 1] = __nv_bfloat162(l2, l3);
}

// ---------------------------------------------------------------------------
// Transpose + split: src [K][N] fp32 -> dst_hi/lo [N][K] bf16.
// ---------------------------------------------------------------------------
__global__ void transpose_split_kernel(const float* __restrict__ src,
                                       __nv_bfloat16* __restrict__ dh,
                                       __nv_bfloat16* __restrict__ dl,
                                       int K, int N)
{
    __shared__ float t[32][33];
    const int k0 = blockIdx.y * 32, n0 = blockIdx.x * 32;
    const int tx = threadIdx.x, ty = threadIdx.y;
#pragma unroll
    for (int i = 0; i < 32; i += 8)
        t[ty + i][tx] = src[(size_t)(k0 + ty + i) * N + n0 + tx];
    __syncthreads();
#pragma unroll
    for (int i = 0; i < 32; i += 8) {
        float v = t[tx][ty + i];
        __nv_bfloat16 h = __float2bfloat16(v);
        float rres = v - __bfloat162float(h);
        size_t o = (size_t)(n0 + ty + i) * K + k0 + tx;
        dh[o] = h;
        dl[o] = __float2bfloat16(rres);
    }
}

// ---------------------------------------------------------------------------
// V transpose+split: v [b][s][kh][d] fp32 -> vt_hi/lo [b][kh][d][s] bf16.
// ---------------------------------------------------------------------------
__global__ void vtrans_split_kernel(const float* __restrict__ v,
                                    __nv_bfloat16* __restrict__ dh,
                                    __nv_bfloat16* __restrict__ dl)
{
    __shared__ float t[32][33];
    const int s0 = blockIdx.x * 32;
    const int d0 = blockIdx.y * 32;
    const int bk = blockIdx.z;              // b * NKH + khead
    const int b = bk / NKH, khead = bk % NKH;
    const int tx = threadIdx.x, ty = threadIdx.y;  // 32 x 8
#pragma unroll
    for (int i = 0; i < 32; i += 8)
        t[ty + i][tx] = v[((size_t)(b * SS + s0 + ty + i) * NKH + khead) * HD + d0 + tx];
    __syncthreads();
#pragma unroll
    for (int i = 0; i < 32; i += 8) {
        float val = t[tx][ty + i];
        __nv_bfloat16 h = __float2bfloat16(val);
        float rres = val - __bfloat162float(h);
        size_t o = ((size_t)(b * NKH + khead) * HD + d0 + ty + i) * SS + s0 + tx;
        dh[o] = h;
        dl[o] = __float2bfloat16(rres);
    }
}

// ---------------------------------------------------------------------------
// RoPE in place.
// ---------------------------------------------------------------------------
__global__ void rope_kernel(float* __restrict__ t,
                            const float* __restrict__ cosb,
                            const float* __restrict__ sinb,
                            int nheads)
{
    int idx = blockIdx.x * blockDim.x + threadIdx.x;
    int total = BB * SS * nheads * (HD / 2);
    if (idx >= total) return;
    int d = idx & 31;
    int rest = idx >> 5;
    int hh = rest % nheads;
    int bs = rest / nheads;
    int s = bs & (SS - 1);

    size_t base = (size_t)bs * nheads * HD + (size_t)hh * HD;
    float c0 = cosb[s * HD + d],      s0 = sinb[s * HD + d];
    float c1 = cosb[s * HD + d + 32], s1 = sinb[s * HD + d + 32];
    float v0 = t[base + d];
    float v1 = t[base + d + 32];
    t[base + d]      = v0 * c0 - v1 * s0;
    t[base + d + 32] = v1 * c1 + v0 * s1;
}

// ---------------------------------------------------------------------------
// HMMA bf16x3 flash attention, causal, GQA. 64x64 tiles, 4 warps.
// Q/K pre-split bf16; V pre-transposed+split [b][kh][d][s].
// smem: Qh,Ql (9216 B each) + 2 stages x (Kh,Kl,Vth,Vtl).
// ---------------------------------------------------------------------------
#define FSTR 72
#define FTILE (64 * FSTR * 2)                 // 9216 B
#define FQ_H 0
#define FQ_L FTILE
#define FSTG(st) (2 * FTILE + (st) * 4 * FTILE)
#define FLASH_SMEM (2 * FTILE + 2 * 4 * FTILE)   // 92160 B

__global__ __launch_bounds__(128) void flash_hmma_kernel(
    const __nv_bfloat16* __restrict__ Qh, const __nv_bfloat16* __restrict__ Ql,
    const __nv_bfloat16* __restrict__ Kh, const __nv_bfloat16* __restrict__ Kl,
    const __nv_bfloat16* __restrict__ Vth, const __nv_bfloat16* __restrict__ Vtl,
    float* __restrict__ O)
{
    extern __shared__ __align__(128) char smem[];
    const uint32_t sb = smem_u32(smem);
    const int tid = threadIdx.x;
    const int wid = tid >> 5;
    const int lane = tid & 31;
    const int qt = blockIdx.x;
    const int h  = blockIdx.y;
    const int b  = blockIdx.z;
    const int q0 = qt * 64;
    const int khead = h >> 2;
    const int warp_m = wid * 16;

    const int er = lane >> 2;
    const int ec = (lane & 3) * 2;
    const int a_r = lane & 15;
    const int a_c = (lane >> 4) * 8;
    const int b_r = lane & 7;
    const int b_c = ((lane >> 3) & 1) * 8;

    // global base pointers
    const __nv_bfloat16* qh_g = Qh + ((size_t)(b * SS + q0) * NH + h) * HD;
    const __nv_bfloat16* ql_g = Ql + ((size_t)(b * SS + q0) * NH + h) * HD;
    const __nv_bfloat16* kh_g = Kh + ((size_t)b * SS * NKH + khead) * HD;
    const __nv_bfloat16* kl_g = Kl + ((size_t)b * SS * NKH + khead) * HD;
    const __nv_bfloat16* vth_g = Vth + (size_t)(b * NKH + khead) * HD * SS;
    const __nv_bfloat16* vtl_g = Vtl + (size_t)(b * NKH + khead) * HD * SS;

    // tile loader: 512 x 16B chunks, 128 threads -> 4 iters
    auto load_tile = [&](const __nv_bfloat16* g, size_t rstride, uint32_t sofs) {
#pragma unroll
        for (int it = 0; it < 4; it++) {
            int ch = tid + it * 128;
            int r = ch >> 3;
            int q8 = ch & 7;
            CP_ASYNC16(sb + sofs + (r * FSTR + q8 * 8) * 2,
                       g + (size_t)r * rstride + q8 * 8);
        }
    };

    // Q + first K/V stage
    load_tile(qh_g, NH * HD, FQ_H);
    load_tile(ql_g, NH * HD, FQ_L);
    load_tile(kh_g, NKH * HD, FSTG(0) + 0 * FTILE);
    load_tile(kl_g, NKH * HD, FSTG(0) + 1 * FTILE);
    load_tile(vth_g, SS, FSTG(0) + 2 * FTILE);
    load_tile(vtl_g, SS, FSTG(0) + 3 * FTILE);
    CP_COMMIT();

    float m[2] = {-1e30f, -1e30f};
    float l[2] = {0.0f, 0.0f};
    float acc[8][4];
#pragma unroll
    for (int i = 0; i < 8; i++)
#pragma unroll
        for (int r = 0; r < 4; r++) acc[i][r] = 0.0f;

    for (int kt = 0; kt <= qt; kt++) {
        const int st = kt & 1;
        const int k0 = kt * 64;
        if (kt < qt) {
            const int kn = (kt + 1) * 64;
            load_tile(kh_g + (size_t)kn * NKH * HD, NKH * HD, FSTG(st ^ 1) + 0 * FTILE);
            load_tile(kl_g + (size_t)kn * NKH * HD, NKH * HD, FSTG(st ^ 1) + 1 * FTILE);
            load_tile(vth_g + kn, SS, FSTG(st ^ 1) + 2 * FTILE);
            load_tile(vtl_g + kn, SS, FSTG(st ^ 1) + 3 * FTILE);
            CP_COMMIT();
            CP_WAIT(1);
        } else {
            CP_WAIT(0);
        }
        __syncthreads();

        const uint32_t sKh = sb + FSTG(st) + 0 * FTILE;
        const uint32_t sKl = sb + FSTG(st) + 1 * FTILE;
        const uint32_t sVh = sb + FSTG(st) + 2 * FTILE;
        const uint32_t sVl = sb + FSTG(st) + 3 * FTILE;

        // ---- S = Q K^T (bf16x3) ----
        float sf[8][4];
#pragma unroll
        for (int nf = 0; nf < 8; nf++)
#pragma unroll
            for (int r = 0; r < 4; r++) sf[nf][r] = 0.0f;

#pragma unroll
        for (int kf = 0; kf < 4; kf++) {
            const int kc = kf * 16;
            uint32_t qah[4], qal[4];
            uint32_t ad = ((warp_m + a_r) * FSTR + kc + a_c) * 2;
            ldsm4(qah[0], qah[1], qah[2], qah[3], sb + FQ_H + ad);
            ldsm4(qal[0], qal[1], qal[2], qal[3], sb + FQ_L + ad);
#pragma unroll
            for (int nf = 0; nf < 8; nf++) {
                uint32_t bd = ((nf * 8 + b_r) * FSTR + kc + b_c) * 2;
                uint32_t kbh[2], kbl[2];
                ldsm2(kbh[0], kbh[1], sKh + bd);
                ldsm2(kbl[0], kbl[1], sKl + bd);
                mma_bf16(sf[nf], qah, kbh);
                mma_bf16(sf[nf], qah, kbl);
                mma_bf16(sf[nf], qal, kbh);
            }
        }

        // ---- scale + mask ----
        const float sc = 0.125f;
        if (kt == qt) {
            const int i0 = warp_m + er;      // local row within 64 == global offset
#pragma unroll
            for (int nf = 0; nf < 8; nf++) {
                int j0 = nf * 8 + ec;
                sf[nf][0] = (j0     <= i0)     ? sf[nf][0] * sc : -1e30f;
                sf[nf][1] = (j0 + 1 <= i0)     ? sf[nf][1] * sc : -1e30f;
                sf[nf][2] = (j0     <= i0 + 8) ? sf[nf][2] * sc : -1e30f;
                sf[nf][3] = (j0 + 1 <= i0 + 8) ? sf[nf][3] * sc : -1e30f;
            }
        } else {
#pragma unroll
            for (int nf = 0; nf < 8; nf++)
#pragma unroll
                for (int r = 0; r < 4; r++) sf[nf][r] *= sc;
        }

        // ---- online softmax (rows er and er+8) ----
        float rmax0 = -1e30f, rmax1 = -1e30f;
#pragma unroll
        for (int nf = 0; nf < 8; nf++) {
            rmax0 = fmaxf(rmax0, fmaxf(sf[nf][0], sf[nf][1]));
            rmax1 = fmaxf(rmax1, fmaxf(sf[nf][2], sf[nf][3]));
        }
        rmax0 = fmaxf(rmax0, __shfl_xor_sync(0xffffffffu, rmax0, 1));
        rmax0 = fmaxf(rmax0, __shfl_xor_sync(0xffffffffu, rmax0, 2));
        rmax1 = fmaxf(rmax1, __shfl_xor_sync(0xffffffffu, rmax1, 1));
        rmax1 = fmaxf(rmax1, __shfl_xor_sync(0xffffffffu, rmax1, 2));

        float nm0 = fmaxf(m[0], rmax0), nm1 = fmaxf(m[1], rmax1);
        float al0 = __expf(m[0] - nm0), al1 = __expf(m[1] - nm1);
        m[0] = nm0; m[1] = nm1;

        float sum0 = 0.0f, sum1 = 0.0f;
#pragma unroll
        for (int nf = 0; nf < 8; nf++) {
            sf[nf][0] = __expf(sf[nf][0] - nm0);
            sf[nf][1] = __expf(sf[nf][1] - nm0);
            sf[nf][2] = __expf(sf[nf][2] - nm1);
            sf[nf][3] = __expf(sf[nf][3] - nm1);
            sum0 += sf[nf][0] + sf[nf][1];
            sum1 += sf[nf][2] + sf[nf][3];
        }
        sum0 += __shfl_xor_sync(0xffffffffu, sum0, 1);
        sum0 += __shfl_xor_sync(0xffffffffu, sum0, 2);
        sum1 += __shfl_xor_sync(0xffffffffu, sum1, 1);
        sum1 += __shfl_xor_sync(0xffffffffu, sum1, 2);
        l[0] = l[0] * al0 + sum0;
        l[1] = l[1] * al1 + sum1;
#pragma unroll
        for (int i = 0; i < 8; i++) {
            acc[i][0] *= al0; acc[i][1] *= al0;
            acc[i][2] *= al1; acc[i][3] *= al1;
        }

        // ---- split P to bf16 hi/lo in A-fragment layout ----
        uint32_t pha[4][4], pla[4][4];
#pragma unroll
        for (int kf = 0; kf < 4; kf++) {
#pragma unroll
            for (int half = 0; half < 2; half++) {
                const float* s2 = sf[kf * 2 + half];
                __nv_bfloat162 h01 = __float22bfloat162_rn(make_float2(s2[0], s2[1]));
                __nv_bfloat162 h23 = __float22bfloat162_rn(make_float2(s2[2], s2[3]));
                __nv_bfloat162 l01 = __float22bfloat162_rn(make_float2(
                    s2[0] - __bfloat162float(h01.x), s2[1] - __bfloat162float(h01.y)));
                __nv_bfloat162 l23 = __float22bfloat162_rn(make_float2(
                    s2[2] - __bfloat162float(h23.x), s2[3] - __bfloat162float(h23.y)));
                pha[kf][half * 2 + 0] = *(uint32_t*)&h01;
                pha[kf][half * 2 + 1] = *(uint32_t*)&h23;
                pla[kf][half * 2 + 0] = *(uint32_t*)&l01;
                pla[kf][half * 2 + 1] = *(uint32_t*)&l23;
            }
        }
        // reorder: a-frag wants {row0_f0, row8_f0, row0_f1, row8_f1} — built above as
        // [f0row0, f0row8, f1row0, f1row8] which is exactly {a0,a1,a2,a3}. OK.

        // ---- O += P V (bf16x3) ----
#pragma unroll
        for (int kf = 0; kf < 4; kf++) {
#pragma unroll
            for (int nf = 0; nf < 8; nf++) {
                uint32_t bd = ((nf * 8 + b_r) * FSTR + kf * 16 + b_c) * 2;
                uint32_t vbh[2], vbl[2];
                ldsm2(vbh[0], vbh[1], sVh + bd);
                ldsm2(vbl[0], vbl[1], sVl + bd);
                mma_bf16(acc[nf], pha[kf], vbh);
                mma_bf16(acc[nf], pha[kf], vbl);
                mma_bf16(acc[nf], pla[kf], vbh);
            }
        }
        __syncthreads();
    }

    // ---- normalize + write O ----
    float inv0 = 1.0f / l[0], inv1 = 1.0f / l[1];
#pragma unroll
    for (int nf = 0; nf < 8; nf++) {
        float* base0 = O + ((size_t)(b * SS + q0 + warp_m + er) * NH + h) * HD + nf * 8 + ec;
        float* base1 = O + ((size_t)(b * SS + q0 + warp_m + er + 8) * NH + h) * HD + nf * 8 + ec;
        *(float2*)base0 = make_float2(acc[nf][0] * inv0, acc[nf][1] * inv0);
        *(float2*)base1 = make_float2(acc[nf][2] * inv1, acc[nf][3] * inv1);
    }
}

// ---------------------------------------------------------------------------
extern "C" void kernel_launch(void* const* d_in, const int* in_sizes, int n_in,
                              void* d_out, int out_size)
{
    const float* x    = (const float*)d_in[0];
    const float* cosb = (const float*)d_in[1];
    const float* sinb = (const float*)d_in[2];
    const float* wq   = (const float*)d_in[3];
    const float* wk   = (const float*)d_in[4];
    const float* wv   = (const float*)d_in[5];
    const float* wo   = (const float*)d_in[6];
    float* out = (float*)d_out;

    float *qp, *kp, *vp, *op;
    cudaGetSymbolAddress((void**)&qp, g_q);
    cudaGetSymbolAddress((void**)&kp, g_k);
    cudaGetSymbolAddress((void**)&vp, g_v);
    cudaGetSymbolAddress((void**)&op, g_o);

    __nv_bfloat16 *xh, *xl, *oh, *ol;
    __nv_bfloat16 *wqh, *wql, *wkh, *wkl, *wvh, *wvl, *woh, *wol;
    __nv_bfloat16 *qh, *ql, *kh2, *kl2, *vth, *vtl;
    cudaGetSymbolAddress((void**)&xh, g_xh);
    cudaGetSymbolAddress((void**)&xl, g_xl);
    cudaGetSymbolAddress((void**)&oh, g_oh);
    cudaGetSymbolAddress((void**)&ol, g_ol);
    cudaGetSymbolAddress((void**)&wqh, g_wqh);
    cudaGetSymbolAddress((void**)&wql, g_wql);
    cudaGetSymbolAddress((void**)&wkh, g_wkh);
    cudaGetSymbolAddress((void**)&wkl, g_wkl);
    cudaGetSymbolAddress((void**)&wvh, g_wvh);
    cudaGetSymbolAddress((void**)&wvl, g_wvl);
    cudaGetSymbolAddress((void**)&woh, g_woh);
    cudaGetSymbolAddress((void**)&wol, g_wol);
    cudaGetSymbolAddress((void**)&qh, g_qh);
    cudaGetSymbolAddress((void**)&ql, g_ql);
    cudaGetSymbolAddress((void**)&kh2, g_kh2);
    cudaGetSymbolAddress((void**)&kl2, g_kl2);
    cudaGetSymbolAddress((void**)&vth, g_vth);
    cudaGetSymbolAddress((void**)&vtl, g_vtl);

    cudaFuncSetAttribute(gemm_bf16x3_kernel,
                         cudaFuncAttributeMaxDynamicSharedMemorySize, GEMM_SMEM);
    cudaFuncSetAttribute(flash_hmma_kernel,
                         cudaFuncAttributeMaxDynamicSharedMemorySize, FLASH_SMEM);

    const int M = BB * SS;  // 4096

    // Split activations, transpose+split weights
    {
        int n4 = M * DMODEL / 4;
        split_kernel<<<(n4 + 255) / 256, 256>>>(
            (const float4*)x, (__nv_bfloat162*)xh, (__nv_bfloat162*)xl, n4);
        dim3 blk(32, 8);
        transpose_split_kernel<<<dim3((NH * HD) / 32, DMODEL / 32), blk>>>(wq, wqh, wql, DMODEL, NH * HD);
        transpose_split_kernel<<<dim3((NKH * HD) / 32, DMODEL / 32), blk>>>(wk, wkh, wkl, DMODEL, NKH * HD);
        transpose_split_kernel<<<dim3((NKH * HD) / 32, DMODEL / 32), blk>>>(wv, wvh, wvl, DMODEL, NKH * HD);
        transpose_split_kernel<<<dim3(DMODEL / 32, (NH * HD) / 32), blk>>>(wo, woh, wol, NH * HD, DMODEL);
    }

    // QKV projections (HMMA bf16x3)
    gemm_bf16x3_kernel<<<dim3((NH * HD) / 128, M / 128), 256, GEMM_SMEM>>>(
        xh, xl, wqh, wql, qp, M, NH * HD, DMODEL);
    gemm_bf16x3_kernel<<<dim3((NKH * HD) / 128, M / 128), 256, GEMM_SMEM>>>(
        xh, xl, wkh, wkl, kp, M, NKH * HD, DMODEL);
    gemm_bf16x3_kernel<<<dim3((NKH * HD) / 128, M / 128), 256, GEMM_SMEM>>>(
        xh, xl, wvh, wvl, vp, M, NKH * HD, DMODEL);

    // RoPE on q and k (fp32, in place)
    {
        int nq = BB * SS * NH * (HD / 2);
        rope_kernel<<<(nq + 255) / 256, 256>>>(qp, cosb, sinb, NH);
        int nk = BB * SS * NKH * (HD / 2);
        rope_kernel<<<(nk + 255) / 256, 256>>>(kp, cosb, sinb, NKH);
    }

    // Split q/k, transpose+split v for flash
    {
        int n4q = M * NH * HD / 4;
        split_kernel<<<(n4q + 255) / 256, 256>>>(
            (const float4*)qp, (__nv_bfloat162*)qh, (__nv_bfloat162*)ql, n4q);
        int n4k = M * NKH * HD / 4;
        split_kernel<<<(n4k + 255) / 256, 256>>>(
            (const float4*)kp, (__nv_bfloat162*)kh2, (__nv_bfloat162*)kl2, n4k);
        dim3 blk(32, 8);
        vtrans_split_kernel<<<dim3(SS / 32, HD / 32, BB * NKH), blk>>>(vp, vth, vtl);
    }

    // Causal GQA flash attention (HMMA bf16x3)
    flash_hmma_kernel<<<dim3(SS / 64, NH, BB), 128, FLASH_SMEM>>>(
        qh, ql, kh2, kl2, vth, vtl, op);

    // Split attention output, then output projection (HMMA bf16x3)
    {
        int n4 = M * (NH * HD) / 4;
        split_kernel<<<(n4 + 255) / 256, 256>>>(
            (const float4*)op, (__nv_bfloat162*)oh, (__nv_bfloat162*)ol, n4);
    }
    gemm_bf16x3_kernel<<<dim3(DMODEL / 128, M / 128), 256, GEMM_SMEM>>>(
        oh, ol, woh, wol, out, M, DMODEL, DMODEL);
}

// round 5
// speedup vs baseline: 2.7401x; 1.5828x over previous
#include <cuda_runtime.h>
#include <cuda_bf16.h>
#include <cstdint>
#include <math.h>

#define BB 2
#define SS 2048
#define DMODEL 1024
#define NH 16
#define NKH 4
#define HD 64

// ---------------------------------------------------------------------------
// Scratch (device globals: allocation-free)
// ---------------------------------------------------------------------------
__device__ float g_q[BB * SS * NH * HD];
__device__ float g_k[BB * SS * NKH * HD];
__device__ float g_v[BB * SS * NKH * HD];

__device__ __nv_bfloat16 g_xh[BB * SS * DMODEL];
__device__ __nv_bfloat16 g_xl[BB * SS * DMODEL];
__device__ __nv_bfloat16 g_oh[BB * SS * NH * HD];
__device__ __nv_bfloat16 g_ol[BB * SS * NH * HD];
__device__ __nv_bfloat16 g_wqh[(NH * HD) * DMODEL];
__device__ __nv_bfloat16 g_wql[(NH * HD) * DMODEL];
__device__ __nv_bfloat16 g_wkh[(NKH * HD) * DMODEL];
__device__ __nv_bfloat16 g_wkl[(NKH * HD) * DMODEL];
__device__ __nv_bfloat16 g_wvh[(NKH * HD) * DMODEL];
__device__ __nv_bfloat16 g_wvl[(NKH * HD) * DMODEL];
__device__ __nv_bfloat16 g_woh[DMODEL * (NH * HD)];
__device__ __nv_bfloat16 g_wol[DMODEL * (NH * HD)];

__device__ __nv_bfloat16 g_qh[BB * SS * NH * HD];
__device__ __nv_bfloat16 g_ql[BB * SS * NH * HD];
__device__ __nv_bfloat16 g_kh2[BB * SS * NKH * HD];
__device__ __nv_bfloat16 g_kl2[BB * SS * NKH * HD];
__device__ __nv_bfloat16 g_vth[BB * NKH * HD * SS];   // [b][kh][d][s]
__device__ __nv_bfloat16 g_vtl[BB * NKH * HD * SS];

// ---------------------------------------------------------------------------
// Warp-level MMA helpers
// ---------------------------------------------------------------------------
__device__ __forceinline__ uint32_t smem_u32(const void* p) {
    uint32_t a;
    asm("{ .reg .u64 t; cvta.to.shared.u64 t, %1; cvt.u32.u64 %0, t; }"
        : "=r"(a) : "l"(p));
    return a;
}

__device__ __forceinline__ void ldsm4(uint32_t& r0, uint32_t& r1,
                                      uint32_t& r2, uint32_t& r3, uint32_t a) {
    asm volatile("ldmatrix.sync.aligned.m8n8.x4.shared.b16 {%0,%1,%2,%3}, [%4];"
                 : "=r"(r0), "=r"(r1), "=r"(r2), "=r"(r3) : "r"(a));
}

__device__ __forceinline__ void ldsm2(uint32_t& r0, uint32_t& r1, uint32_t a) {
    asm volatile("ldmatrix.sync.aligned.m8n8.x2.shared.b16 {%0,%1}, [%2];"
                 : "=r"(r0), "=r"(r1) : "r"(a));
}

__device__ __forceinline__ void mma_bf16(float* c, const uint32_t* a,
                                         const uint32_t* b) {
    asm volatile(
        "mma.sync.aligned.m16n8k16.row.col.f32.bf16.bf16.f32 "
        "{%0,%1,%2,%3}, {%4,%5,%6,%7}, {%8,%9}, {%0,%1,%2,%3};"
        : "+f"(c[0]), "+f"(c[1]), "+f"(c[2]), "+f"(c[3])
        : "r"(a[0]), "r"(a[1]), "r"(a[2]), "r"(a[3]), "r"(b[0]), "r"(b[1]));
}

#define CP_ASYNC16(sa, ga) \
    asm volatile("cp.async.cg.shared.global [%0], [%1], 16;" \
                 :: "r"(sa), "l"(ga))
#define CP_COMMIT() asm volatile("cp.async.commit_group;")
#define CP_WAIT(N)  asm volatile("cp.async.wait_group %0;" :: "n"(N))

// ---------------------------------------------------------------------------
// bf16x3 HMMA GEMM (unchanged, passing)
// ---------------------------------------------------------------------------
#define BK 32
#define GSTRIDE 40
#define GTILE_B (128 * GSTRIDE * 2)
#define GOFF(t, st) (((st) * 4 + (t)) * GTILE_B)
#define GEMM_SMEM (8 * GTILE_B)

__global__ __launch_bounds__(256) void gemm_bf16x3_kernel(
    const __nv_bfloat16* __restrict__ Ah, const __nv_bfloat16* __restrict__ Al,
    const __nv_bfloat16* __restrict__ Bh, const __nv_bfloat16* __restrict__ Bl,
    float* __restrict__ C, int M, int N, int K)
{
    extern __shared__ __align__(128) char smem[];
    const uint32_t sb = smem_u32(smem);
    const int tid = threadIdx.x;
    const int wid = tid >> 5;
    const int lane = tid & 31;
    const int bm = blockIdx.y * 128;
    const int bn = blockIdx.x * 128;
    const int warp_m = (wid >> 2) * 64;
    const int warp_n = (wid & 3) * 32;

    const __nv_bfloat16* gp[4] = {
        Ah + (size_t)bm * K, Al + (size_t)bm * K,
        Bh + (size_t)bn * K, Bl + (size_t)bn * K };

    const int lrow0 = tid >> 2;
    const int lq = tid & 3;

    auto load_stage = [&](int c, int st) {
#pragma unroll
        for (int t = 0; t < 4; t++) {
            const __nv_bfloat16* P = gp[t] + (size_t)c * BK;
#pragma unroll
            for (int it = 0; it < 2; it++) {
                int row = lrow0 + it * 64;
                uint32_t sa = sb + GOFF(t, st) + (row * GSTRIDE + lq * 8) * 2;
                CP_ASYNC16(sa, P + (size_t)row * K + lq * 8);
            }
        }
        CP_COMMIT();
    };

    float acc[4][4][4];
#pragma unroll
    for (int i = 0; i < 4; i++)
#pragma unroll
        for (int j = 0; j < 4; j++)
#pragma unroll
            for (int r = 0; r < 4; r++) acc[i][j][r] = 0.0f;

    const int nchunk = K / BK;
    load_stage(0, 0);

    const int a_r = lane & 15;
    const int a_c = (lane >> 4) * 8;
    const int b_r = lane & 7;
    const int b_c = ((lane >> 3) & 1) * 8;

    for (int c = 0; c < nchunk; c++) {
        const int st = c & 1;
        if (c + 1 < nchunk) {
            load_stage(c + 1, st ^ 1);
            CP_WAIT(1);
        } else {
            CP_WAIT(0);
        }
        __syncthreads();

        const uint32_t sAh = sb + GOFF(0, st);
        const uint32_t sAl = sb + GOFF(1, st);
        const uint32_t sBh = sb + GOFF(2, st);
        const uint32_t sBl = sb + GOFF(3, st);

#pragma unroll
        for (int kf = 0; kf < 2; kf++) {
            const int kc = kf * 16;
            uint32_t ah[4][4], al[4][4], bh[4][2], bl[4][2];
#pragma unroll
            for (int mf = 0; mf < 4; mf++) {
                uint32_t ad = ((warp_m + mf * 16 + a_r) * GSTRIDE + kc + a_c) * 2;
                ldsm4(ah[mf][0], ah[mf][1], ah[mf][2], ah[mf][3], sAh + ad);
            }
#pragma unroll
            for (int nf = 0; nf < 4; nf++) {
                uint32_t bd = ((warp_n + nf * 8 + b_r) * GSTRIDE + kc + b_c) * 2;
                ldsm2(bh[nf][0], bh[nf][1], sBh + bd);
            }
#pragma unroll
            for (int mf = 0; mf < 4; mf++)
#pragma unroll
                for (int nf = 0; nf < 4; nf++)
                    mma_bf16(acc[mf][nf], ah[mf], bh[nf]);

#pragma unroll
            for (int nf = 0; nf < 4; nf++) {
                uint32_t bd = ((warp_n + nf * 8 + b_r) * GSTRIDE + kc + b_c) * 2;
                ldsm2(bl[nf][0], bl[nf][1], sBl + bd);
            }
#pragma unroll
            for (int mf = 0; mf < 4; mf++)
#pragma unroll
                for (int nf = 0; nf < 4; nf++)
                    mma_bf16(acc[mf][nf], ah[mf], bl[nf]);

#pragma unroll
            for (int mf = 0; mf < 4; mf++) {
                uint32_t ad = ((warp_m + mf * 16 + a_r) * GSTRIDE + kc + a_c) * 2;
                ldsm4(al[mf][0], al[mf][1], al[mf][2], al[mf][3], sAl + ad);
            }
#pragma unroll
            for (int mf = 0; mf < 4; mf++)
#pragma unroll
                for (int nf = 0; nf < 4; nf++)
                    mma_bf16(acc[mf][nf], al[mf], bh[nf]);
        }
        __syncthreads();
    }

    const int er = lane >> 2;
    const int ec = (lane & 3) * 2;
#pragma unroll
    for (int mf = 0; mf < 4; mf++) {
#pragma unroll
        for (int nf = 0; nf < 4; nf++) {
            float* base = C + (size_t)(bm + warp_m + mf * 16 + er) * N
                            + bn + warp_n + nf * 8 + ec;
            *(float2*)base = make_float2(acc[mf][nf][0], acc[mf][nf][1]);
            *(float2*)(base + 8 * N) = make_float2(acc[mf][nf][2], acc[mf][nf][3]);
        }
    }
}

// ---------------------------------------------------------------------------
// Elementwise split fp32 -> (hi, lo) bf16.
// ---------------------------------------------------------------------------
__global__ void split_kernel(const float4* __restrict__ src,
                             __nv_bfloat162* __restrict__ dh,
                             __nv_bfloat162* __restrict__ dl, int n4)
{
    int i = blockIdx.x * blockDim.x + threadIdx.x;
    if (i >= n4) return;
    float4 v = src[i];
    __nv_bfloat16 h0 = __float2bfloat16(v.x);
    __nv_bfloat16 h1 = __float2bfloat16(v.y);
    __nv_bfloat16 h2 = __float2bfloat16(v.z);
    __nv_bfloat16 h3 = __float2bfloat16(v.w);
    dh[2 * i]     = __nv_bfloat162(h0, h1);
    dh[2 * i + 1] = __nv_bfloat162(h2, h3);
    __nv_bfloat16 l0 = __float2bfloat16(v.x - __bfloat162float(h0));
    __nv_bfloat16 l1 = __float2bfloat16(v.y - __bfloat162float(h1));
    __nv_bfloat16 l2 = __float2bfloat16(v.z - __bfloat162float(h2));
    __nv_bfloat16 l3 = __float2bfloat16(v.w - __bfloat162float(h3));
    dl[2 * i]     = __nv_bfloat162(l0, l1);
    dl[2 * i + 1] = __nv_bfloat162(l2, l3);
}

// ---------------------------------------------------------------------------
// Transpose + split: src [K][N] fp32 -> dst_hi/lo [N][K] bf16.
// ---------------------------------------------------------------------------
__global__ void transpose_split_kernel(const float* __restrict__ src,
                                       __nv_bfloat16* __restrict__ dh,
                                       __nv_bfloat16* __restrict__ dl,
                                       int K, int N)
{
    __shared__ float t[32][33];
    const int k0 = blockIdx.y * 32, n0 = blockIdx.x * 32;
    const int tx = threadIdx.x, ty = threadIdx.y;
#pragma unroll
    for (int i = 0; i < 32; i += 8)
        t[ty + i][tx] = src[(size_t)(k0 + ty + i) * N + n0 + tx];
    __syncthreads();
#pragma unroll
    for (int i = 0; i < 32; i += 8) {
        float v = t[tx][ty + i];
        __nv_bfloat16 h = __float2bfloat16(v);
        float rres = v - __bfloat162float(h);
        size_t o = (size_t)(n0 + ty + i) * K + k0 + tx;
        dh[o] = h;
        dl[o] = __float2bfloat16(rres);
    }
}

// ---------------------------------------------------------------------------
// V transpose+split: v [b][s][kh][d] fp32 -> vt_hi/lo [b][kh][d][s] bf16.
// ---------------------------------------------------------------------------
__global__ void vtrans_split_kernel(const float* __restrict__ v,
                                    __nv_bfloat16* __restrict__ dh,
                                    __nv_bfloat16* __restrict__ dl)
{
    __shared__ float t[32][33];
    const int s0 = blockIdx.x * 32;
    const int d0 = blockIdx.y * 32;
    const int bk = blockIdx.z;
    const int b = bk / NKH, khead = bk % NKH;
    const int tx = threadIdx.x, ty = threadIdx.y;
#pragma unroll
    for (int i = 0; i < 32; i += 8)
        t[ty + i][tx] = v[((size_t)(b * SS + s0 + ty + i) * NKH + khead) * HD + d0 + tx];
    __syncthreads();
#pragma unroll
    for (int i = 0; i < 32; i += 8) {
        float val = t[tx][ty + i];
        __nv_bfloat16 h = __float2bfloat16(val);
        float rres = val - __bfloat162float(h);
        size_t o = ((size_t)(b * NKH + khead) * HD + d0 + ty + i) * SS + s0 + tx;
        dh[o] = h;
        dl[o] = __float2bfloat16(rres);
    }
}

// ---------------------------------------------------------------------------
// RoPE + split: reads fp32 t, writes split bf16 hi/lo directly.
// ---------------------------------------------------------------------------
__global__ void rope_split_kernel(const float* __restrict__ t,
                                  const float* __restrict__ cosb,
                                  const float* __restrict__ sinb,
                                  __nv_bfloat16* __restrict__ th,
                                  __nv_bfloat16* __restrict__ tl,
                                  int nheads)
{
    int idx = blockIdx.x * blockDim.x + threadIdx.x;
    int total = BB * SS * nheads * (HD / 2);
    if (idx >= total) return;
    int d = idx & 31;
    int rest = idx >> 5;
    int hh = rest % nheads;
    int bs = rest / nheads;
    int s = bs & (SS - 1);

    size_t base = (size_t)bs * nheads * HD + (size_t)hh * HD;
    float c0 = cosb[s * HD + d],      s0 = sinb[s * HD + d];
    float c1 = cosb[s * HD + d + 32], s1 = sinb[s * HD + d + 32];
    float v0 = t[base + d];
    float v1 = t[base + d + 32];
    float r0 = v0 * c0 - v1 * s0;
    float r1 = v1 * c1 + v0 * s1;

    __nv_bfloat16 h0 = __float2bfloat16(r0);
    __nv_bfloat16 h1 = __float2bfloat16(r1);
    th[base + d]      = h0;
    th[base + d + 32] = h1;
    tl[base + d]      = __float2bfloat16(r0 - __bfloat162float(h0));
    tl[base + d + 32] = __float2bfloat16(r1 - __bfloat162float(h1));
}

// ---------------------------------------------------------------------------
// HMMA bf16x3 flash attention, causal, GQA.
// BLOCK_M=128 (8 warps), BLOCK_N=64; ldsm4 B-fragments; writes Oh/Ol bf16.
// ---------------------------------------------------------------------------
#define FSTR 72
#define FTILE64 (64 * FSTR * 2)                 // 9216 B
#define FQ_TILE (128 * FSTR * 2)                // 18432 B
#define FQ_H 0
#define FQ_L FQ_TILE
#define FSTG(st) (2 * FQ_TILE + (st) * 4 * FTILE64)
#define FLASH_SMEM (2 * FQ_TILE + 2 * 4 * FTILE64)   // 110592 B

__global__ __launch_bounds__(256) void flash_hmma_kernel(
    const __nv_bfloat16* __restrict__ Qh, const __nv_bfloat16* __restrict__ Ql,
    const __nv_bfloat16* __restrict__ Kh, const __nv_bfloat16* __restrict__ Kl,
    const __nv_bfloat16* __restrict__ Vth, const __nv_bfloat16* __restrict__ Vtl,
    __nv_bfloat16* __restrict__ Oh, __nv_bfloat16* __restrict__ Ol)
{
    extern __shared__ __align__(128) char smem[];
    const uint32_t sb = smem_u32(smem);
    const int tid = threadIdx.x;
    const int wid = tid >> 5;
    const int lane = tid & 31;
    const int qt = blockIdx.x;
    const int h  = blockIdx.y;
    const int b  = blockIdx.z;
    const int q0 = qt * 128;
    const int khead = h >> 2;
    const int warp_m = wid * 16;

    const int er = lane >> 2;
    const int ec = (lane & 3) * 2;
    const int a_r = lane & 15;
    const int a_c = (lane >> 4) * 8;
    // ldsm4 B-fragment addressing (covers 16 n-rows, 16 k-cols)
    const int g4 = lane >> 3;
    const int b4_r = (g4 >> 1) * 8 + (lane & 7);
    const int b4_c = (g4 & 1) * 8;

    const __nv_bfloat16* qh_g = Qh + ((size_t)(b * SS + q0) * NH + h) * HD;
    const __nv_bfloat16* ql_g = Ql + ((size_t)(b * SS + q0) * NH + h) * HD;
    const __nv_bfloat16* kh_g = Kh + ((size_t)b * SS * NKH + khead) * HD;
    const __nv_bfloat16* kl_g = Kl + ((size_t)b * SS * NKH + khead) * HD;
    const __nv_bfloat16* vth_g = Vth + (size_t)(b * NKH + khead) * HD * SS;
    const __nv_bfloat16* vtl_g = Vtl + (size_t)(b * NKH + khead) * HD * SS;

    // 64-row tile loader: 512 x 16B chunks, 256 threads -> 2 iters
    auto load_tile64 = [&](const __nv_bfloat16* g, size_t rstride, uint32_t sofs) {
#pragma unroll
        for (int it = 0; it < 2; it++) {
            int ch = tid + it * 256;
            int r = ch >> 3;
            int q8 = ch & 7;
            CP_ASYNC16(sb + sofs + (r * FSTR + q8 * 8) * 2,
                       g + (size_t)r * rstride + q8 * 8);
        }
    };
    // 128-row Q loader: 1024 chunks -> 4 iters
    auto load_q = [&](const __nv_bfloat16* g, uint32_t sofs) {
#pragma unroll
        for (int it = 0; it < 4; it++) {
            int ch = tid + it * 256;
            int r = ch >> 3;
            int q8 = ch & 7;
            CP_ASYNC16(sb + sofs + (r * FSTR + q8 * 8) * 2,
                       g + (size_t)r * (NH * HD) + q8 * 8);
        }
    };

    load_q(qh_g, FQ_H);
    load_q(ql_g, FQ_L);
    load_tile64(kh_g, NKH * HD, FSTG(0) + 0 * FTILE64);
    load_tile64(kl_g, NKH * HD, FSTG(0) + 1 * FTILE64);
    load_tile64(vth_g, SS, FSTG(0) + 2 * FTILE64);
    load_tile64(vtl_g, SS, FSTG(0) + 3 * FTILE64);
    CP_COMMIT();

    float m[2] = {-1e30f, -1e30f};
    float l[2] = {0.0f, 0.0f};
    float acc[8][4];
#pragma unroll
    for (int i = 0; i < 8; i++)
#pragma unroll
        for (int r = 0; r < 4; r++) acc[i][r] = 0.0f;

    const int kt_end = 2 * qt + 1;

    for (int kt = 0; kt <= kt_end; kt++) {
        const int st = kt & 1;
        if (kt < kt_end) {
            const int kn = (kt + 1) * 64;
            load_tile64(kh_g + (size_t)kn * NKH * HD, NKH * HD, FSTG(st ^ 1) + 0 * FTILE64);
            load_tile64(kl_g + (size_t)kn * NKH * HD, NKH * HD, FSTG(st ^ 1) + 1 * FTILE64);
            load_tile64(vth_g + kn, SS, FSTG(st ^ 1) + 2 * FTILE64);
            load_tile64(vtl_g + kn, SS, FSTG(st ^ 1) + 3 * FTILE64);
            CP_COMMIT();
            CP_WAIT(1);
        } else {
            CP_WAIT(0);
        }
        __syncthreads();

        const int row_lo = q0 + warp_m;           // this warp's first q row
        const bool any  = (kt * 64     <= row_lo + 15);
        const bool full = (kt * 64 + 63 <= row_lo);

        if (any) {
            const uint32_t sKh = sb + FSTG(st) + 0 * FTILE64;
            const uint32_t sKl = sb + FSTG(st) + 1 * FTILE64;
            const uint32_t sVh = sb + FSTG(st) + 2 * FTILE64;
            const uint32_t sVl = sb + FSTG(st) + 3 * FTILE64;

            // ---- S = Q K^T (bf16x3) ----
            float sf[8][4];
#pragma unroll
            for (int nf = 0; nf < 8; nf++)
#pragma unroll
                for (int r = 0; r < 4; r++) sf[nf][r] = 0.0f;

#pragma unroll
            for (int kf = 0; kf < 4; kf++) {
                const int kc = kf * 16;
                uint32_t qah[4], qal[4];
                uint32_t ad = ((warp_m + a_r) * FSTR + kc + a_c) * 2;
                ldsm4(qah[0], qah[1], qah[2], qah[3], sb + FQ_H + ad);
                ldsm4(qal[0], qal[1], qal[2], qal[3], sb + FQ_L + ad);
#pragma unroll
                for (int np = 0; np < 4; np++) {
                    uint32_t bd = ((np * 16 + b4_r) * FSTR + kc + b4_c) * 2;
                    uint32_t kbh[4], kbl[4];
                    ldsm4(kbh[0], kbh[1], kbh[2], kbh[3], sKh + bd);
                    ldsm4(kbl[0], kbl[1], kbl[2], kbl[3], sKl + bd);
                    mma_bf16(sf[np * 2],     qah, kbh);
                    mma_bf16(sf[np * 2],     qah, kbl);
                    mma_bf16(sf[np * 2],     qal, kbh);
                    mma_bf16(sf[np * 2 + 1], qah, kbh + 2);
                    mma_bf16(sf[np * 2 + 1], qah, kbl + 2);
                    mma_bf16(sf[np * 2 + 1], qal, kbh + 2);
                }
            }

            // ---- scale + mask ----
            const float sc = 0.125f;
            if (!full) {
                const int i0 = row_lo + er;
#pragma unroll
                for (int nf = 0; nf < 8; nf++) {
                    int j0 = kt * 64 + nf * 8 + ec;
                    sf[nf][0] = (j0     <= i0)     ? sf[nf][0] * sc : -1e30f;
                    sf[nf][1] = (j0 + 1 <= i0)     ? sf[nf][1] * sc : -1e30f;
                    sf[nf][2] = (j0     <= i0 + 8) ? sf[nf][2] * sc : -1e30f;
                    sf[nf][3] = (j0 + 1 <= i0 + 8) ? sf[nf][3] * sc : -1e30f;
                }
            } else {
#pragma unroll
                for (int nf = 0; nf < 8; nf++)
#pragma unroll
                    for (int r = 0; r < 4; r++) sf[nf][r] *= sc;
            }

            // ---- online softmax ----
            float rmax0 = -1e30f, rmax1 = -1e30f;
#pragma unroll
            for (int nf = 0; nf < 8; nf++) {
                rmax0 = fmaxf(rmax0, fmaxf(sf[nf][0], sf[nf][1]));
                rmax1 = fmaxf(rmax1, fmaxf(sf[nf][2], sf[nf][3]));
            }
            rmax0 = fmaxf(rmax0, __shfl_xor_sync(0xffffffffu, rmax0, 1));
            rmax0 = fmaxf(rmax0, __shfl_xor_sync(0xffffffffu, rmax0, 2));
            rmax1 = fmaxf(rmax1, __shfl_xor_sync(0xffffffffu, rmax1, 1));
            rmax1 = fmaxf(rmax1, __shfl_xor_sync(0xffffffffu, rmax1, 2));

            float nm0 = fmaxf(m[0], rmax0), nm1 = fmaxf(m[1], rmax1);
            float al0 = __expf(m[0] - nm0), al1 = __expf(m[1] - nm1);
            m[0] = nm0; m[1] = nm1;

            float sum0 = 0.0f, sum1 = 0.0f;
#pragma unroll
            for (int nf = 0; nf < 8; nf++) {
                sf[nf][0] = __expf(sf[nf][0] - nm0);
                sf[nf][1] = __expf(sf[nf][1] - nm0);
                sf[nf][2] = __expf(sf[nf][2] - nm1);
                sf[nf][3] = __expf(sf[nf][3] - nm1);
                sum0 += sf[nf][0] + sf[nf][1];
                sum1 += sf[nf][2] + sf[nf][3];
            }
            sum0 += __shfl_xor_sync(0xffffffffu, sum0, 1);
            sum0 += __shfl_xor_sync(0xffffffffu, sum0, 2);
            sum1 += __shfl_xor_sync(0xffffffffu, sum1, 1);
            sum1 += __shfl_xor_sync(0xffffffffu, sum1, 2);
            l[0] = l[0] * al0 + sum0;
            l[1] = l[1] * al1 + sum1;
#pragma unroll
            for (int i = 0; i < 8; i++) {
                acc[i][0] *= al0; acc[i][1] *= al0;
                acc[i][2] *= al1; acc[i][3] *= al1;
            }

            // ---- split P to bf16 hi/lo (A-fragment layout) ----
            uint32_t pha[4][4], pla[4][4];
#pragma unroll
            for (int kf = 0; kf < 4; kf++) {
#pragma unroll
                for (int half = 0; half < 2; half++) {
                    const float* s2 = sf[kf * 2 + half];
                    __nv_bfloat162 h01 = __float22bfloat162_rn(make_float2(s2[0], s2[1]));
                    __nv_bfloat162 h23 = __float22bfloat162_rn(make_float2(s2[2], s2[3]));
                    __nv_bfloat162 l01 = __float22bfloat162_rn(make_float2(
                        s2[0] - __bfloat162float(h01.x), s2[1] - __bfloat162float(h01.y)));
                    __nv_bfloat162 l23 = __float22bfloat162_rn(make_float2(
                        s2[2] - __bfloat162float(h23.x), s2[3] - __bfloat162float(h23.y)));
                    pha[kf][half * 2 + 0] = *(uint32_t*)&h01;
                    pha[kf][half * 2 + 1] = *(uint32_t*)&h23;
                    pla[kf][half * 2 + 0] = *(uint32_t*)&l01;
                    pla[kf][half * 2 + 1] = *(uint32_t*)&l23;
                }
            }

            // ---- O += P V (bf16x3) ----
#pragma unroll
            for (int kf = 0; kf < 4; kf++) {
#pragma unroll
                for (int np = 0; np < 4; np++) {
                    uint32_t bd = ((np * 16 + b4_r) * FSTR + kf * 16 + b4_c) * 2;
                    uint32_t vbh[4], vbl[4];
                    ldsm4(vbh[0], vbh[1], vbh[2], vbh[3], sVh + bd);
                    ldsm4(vbl[0], vbl[1], vbl[2], vbl[3], sVl + bd);
                    mma_bf16(acc[np * 2],     pha[kf], vbh);
                    mma_bf16(acc[np * 2],     pha[kf], vbl);
                    mma_bf16(acc[np * 2],     pla[kf], vbh);
                    mma_bf16(acc[np * 2 + 1], pha[kf], vbh + 2);
                    mma_bf16(acc[np * 2 + 1], pha[kf], vbl + 2);
                    mma_bf16(acc[np * 2 + 1], pla[kf], vbh + 2);
                }
            }
        }
        __syncthreads();
    }

    // ---- normalize + split + write Oh/Ol ----
    float inv0 = 1.0f / l[0], inv1 = 1.0f / l[1];
#pragma unroll
    for (int nf = 0; nf < 8; nf++) {
        size_t o0 = ((size_t)(b * SS + q0 + warp_m + er) * NH + h) * HD + nf * 8 + ec;
        size_t o1 = ((size_t)(b * SS + q0 + warp_m + er + 8) * NH + h) * HD + nf * 8 + ec;
        float v00 = acc[nf][0] * inv0, v01 = acc[nf][1] * inv0;
        float v10 = acc[nf][2] * inv1, v11 = acc[nf][3] * inv1;
        __nv_bfloat162 h0 = __float22bfloat162_rn(make_float2(v00, v01));
        __nv_bfloat162 h1 = __float22bfloat162_rn(make_float2(v10, v11));
        __nv_bfloat162 l0 = __float22bfloat162_rn(make_float2(
            v00 - __bfloat162float(h0.x), v01 - __bfloat162float(h0.y)));
        __nv_bfloat162 l1 = __float22bfloat162_rn(make_float2(
            v10 - __bfloat162float(h1.x), v11 - __bfloat162float(h1.y)));
        *(uint32_t*)(Oh + o0) = *(uint32_t*)&h0;
        *(uint32_t*)(Oh + o1) = *(uint32_t*)&h1;
        *(uint32_t*)(Ol + o0) = *(uint32_t*)&l0;
        *(uint32_t*)(Ol + o1) = *(uint32_t*)&l1;
    }
}

// ---------------------------------------------------------------------------
extern "C" void kernel_launch(void* const* d_in, const int* in_sizes, int n_in,
                              void* d_out, int out_size)
{
    const float* x    = (const float*)d_in[0];
    const float* cosb = (const float*)d_in[1];
    const float* sinb = (const float*)d_in[2];
    const float* wq   = (const float*)d_in[3];
    const float* wk   = (const float*)d_in[4];
    const float* wv   = (const float*)d_in[5];
    const float* wo   = (const float*)d_in[6];
    float* out = (float*)d_out;

    float *qp, *kp, *vp;
    cudaGetSymbolAddress((void**)&qp, g_q);
    cudaGetSymbolAddress((void**)&kp, g_k);
    cudaGetSymbolAddress((void**)&vp, g_v);

    __nv_bfloat16 *xh, *xl, *oh, *ol;
    __nv_bfloat16 *wqh, *wql, *wkh, *wkl, *wvh, *wvl, *woh, *wol;
    __nv_bfloat16 *qh, *ql, *kh2, *kl2, *vth, *vtl;
    cudaGetSymbolAddress((void**)&xh, g_xh);
    cudaGetSymbolAddress((void**)&xl, g_xl);
    cudaGetSymbolAddress((void**)&oh, g_oh);
    cudaGetSymbolAddress((void**)&ol, g_ol);
    cudaGetSymbolAddress((void**)&wqh, g_wqh);
    cudaGetSymbolAddress((void**)&wql, g_wql);
    cudaGetSymbolAddress((void**)&wkh, g_wkh);
    cudaGetSymbolAddress((void**)&wkl, g_wkl);
    cudaGetSymbolAddress((void**)&wvh, g_wvh);
    cudaGetSymbolAddress((void**)&wvl, g_wvl);
    cudaGetSymbolAddress((void**)&woh, g_woh);
    cudaGetSymbolAddress((void**)&wol, g_wol);
    cudaGetSymbolAddress((void**)&qh, g_qh);
    cudaGetSymbolAddress((void**)&ql, g_ql);
    cudaGetSymbolAddress((void**)&kh2, g_kh2);
    cudaGetSymbolAddress((void**)&kl2, g_kl2);
    cudaGetSymbolAddress((void**)&vth, g_vth);
    cudaGetSymbolAddress((void**)&vtl, g_vtl);

    cudaFuncSetAttribute(gemm_bf16x3_kernel,
                         cudaFuncAttributeMaxDynamicSharedMemorySize, GEMM_SMEM);
    cudaFuncSetAttribute(flash_hmma_kernel,
                         cudaFuncAttributeMaxDynamicSharedMemorySize, FLASH_SMEM);

    const int M = BB * SS;  // 4096

    // Split activations, transpose+split weights
    {
        int n4 = M * DMODEL / 4;
        split_kernel<<<(n4 + 255) / 256, 256>>>(
            (const float4*)x, (__nv_bfloat162*)xh, (__nv_bfloat162*)xl, n4);
        dim3 blk(32, 8);
        transpose_split_kernel<<<dim3((NH * HD) / 32, DMODEL / 32), blk>>>(wq, wqh, wql, DMODEL, NH * HD);
        transpose_split_kernel<<<dim3((NKH * HD) / 32, DMODEL / 32), blk>>>(wk, wkh, wkl, DMODEL, NKH * HD);
        transpose_split_kernel<<<dim3((NKH * HD) / 32, DMODEL / 32), blk>>>(wv, wvh, wvl, DMODEL, NKH * HD);
        transpose_split_kernel<<<dim3(DMODEL / 32, (NH * HD) / 32), blk>>>(wo, woh, wol, NH * HD, DMODEL);
    }

    // QKV projections (HMMA bf16x3)
    gemm_bf16x3_kernel<<<dim3((NH * HD) / 128, M / 128), 256, GEMM_SMEM>>>(
        xh, xl, wqh, wql, qp, M, NH * HD, DMODEL);
    gemm_bf16x3_kernel<<<dim3((NKH * HD) / 128, M / 128), 256, GEMM_SMEM>>>(
        xh, xl, wkh, wkl, kp, M, NKH * HD, DMODEL);
    gemm_bf16x3_kernel<<<dim3((NKH * HD) / 128, M / 128), 256, GEMM_SMEM>>>(
        xh, xl, wvh, wvl, vp, M, NKH * HD, DMODEL);

    // RoPE + split (q, k); V transpose + split
    {
        int nq = BB * SS * NH * (HD / 2);
        rope_split_kernel<<<(nq + 255) / 256, 256>>>(qp, cosb, sinb, qh, ql, NH);
        int nk = BB * SS * NKH * (HD / 2);
        rope_split_kernel<<<(nk + 255) / 256, 256>>>(kp, cosb, sinb, kh2, kl2, NKH);
        dim3 blk(32, 8);
        vtrans_split_kernel<<<dim3(SS / 32, HD / 32, BB * NKH), blk>>>(vp, vth, vtl);
    }

    // Causal GQA flash attention (HMMA bf16x3), writes Oh/Ol bf16
    flash_hmma_kernel<<<dim3(SS / 128, NH, BB), 256, FLASH_SMEM>>>(
        qh, ql, kh2, kl2, vth, vtl, oh, ol);

    // Output projection (HMMA bf16x3)
    gemm_bf16x3_kernel<<<dim3(DMODEL / 128, M / 128), 256, GEMM_SMEM>>>(
        oh, ol, woh, wol, out, M, DMODEL, DMODEL);
}

// round 6
// speedup vs baseline: 3.0975x; 1.1304x over previous
#include <cuda_runtime.h>
#include <cuda_bf16.h>
#include <cstdint>
#include <math.h>

#define BB 2
#define SS 2048
#define DMODEL 1024
#define NH 16
#define NKH 4
#define HD 64
#define NQKV 1536   // NH*HD + NKH*HD + NKH*HD

// ---------------------------------------------------------------------------
// Scratch (device globals: allocation-free)
// ---------------------------------------------------------------------------
__device__ float g_qkv[BB * SS * NQKV];               // fused q|k|v fp32

__device__ __nv_bfloat16 g_xh[BB * SS * DMODEL];
__device__ __nv_bfloat16 g_xl[BB * SS * DMODEL];
__device__ __nv_bfloat16 g_oh[BB * SS * NH * HD];
__device__ __nv_bfloat16 g_ol[BB * SS * NH * HD];
__device__ __nv_bfloat16 g_wqkvh[NQKV * DMODEL];      // wq|wk|wv rows, [N][K]
__device__ __nv_bfloat16 g_wqkvl[NQKV * DMODEL];
__device__ __nv_bfloat16 g_woh[DMODEL * (NH * HD)];
__device__ __nv_bfloat16 g_wol[DMODEL * (NH * HD)];

__device__ __nv_bfloat16 g_qh[BB * SS * NH * HD];
__device__ __nv_bfloat16 g_ql[BB * SS * NH * HD];
__device__ __nv_bfloat16 g_kh2[BB * SS * NKH * HD];
__device__ __nv_bfloat16 g_kl2[BB * SS * NKH * HD];
__device__ __nv_bfloat16 g_vth[BB * NKH * HD * SS];   // [b][kh][d][s]
__device__ __nv_bfloat16 g_vtl[BB * NKH * HD * SS];

// ---------------------------------------------------------------------------
// Warp-level MMA helpers
// ---------------------------------------------------------------------------
__device__ __forceinline__ uint32_t smem_u32(const void* p) {
    uint32_t a;
    asm("{ .reg .u64 t; cvta.to.shared.u64 t, %1; cvt.u32.u64 %0, t; }"
        : "=r"(a) : "l"(p));
    return a;
}

__device__ __forceinline__ void ldsm4(uint32_t& r0, uint32_t& r1,
                                      uint32_t& r2, uint32_t& r3, uint32_t a) {
    asm volatile("ldmatrix.sync.aligned.m8n8.x4.shared.b16 {%0,%1,%2,%3}, [%4];"
                 : "=r"(r0), "=r"(r1), "=r"(r2), "=r"(r3) : "r"(a));
}

__device__ __forceinline__ void mma_bf16(float* c, const uint32_t* a,
                                         const uint32_t* b) {
    asm volatile(
        "mma.sync.aligned.m16n8k16.row.col.f32.bf16.bf16.f32 "
        "{%0,%1,%2,%3}, {%4,%5,%6,%7}, {%8,%9}, {%0,%1,%2,%3};"
        : "+f"(c[0]), "+f"(c[1]), "+f"(c[2]), "+f"(c[3])
        : "r"(a[0]), "r"(a[1]), "r"(a[2]), "r"(a[3]), "r"(b[0]), "r"(b[1]));
}

#define CP_ASYNC16(sa, ga) \
    asm volatile("cp.async.cg.shared.global [%0], [%1], 16;" \
                 :: "r"(sa), "l"(ga))
#define CP_COMMIT() asm volatile("cp.async.commit_group;")
#define CP_WAIT(N)  asm volatile("cp.async.wait_group %0;" :: "n"(N))

// ---------------------------------------------------------------------------
// bf16x3 HMMA GEMM: C[M,N] = A[M,K] @ B[N,K]^T.
// 128x128 CTA tile, BK=32, 8 warps (2x4), ldsm4 A+B fragments, 2-stage.
// ---------------------------------------------------------------------------
#define BK 32
#define GSTRIDE 40
#define GTILE_B (128 * GSTRIDE * 2)
#define GOFF(t, st) (((st) * 4 + (t)) * GTILE_B)
#define GEMM_SMEM (8 * GTILE_B)

__global__ __launch_bounds__(256) void gemm_bf16x3_kernel(
    const __nv_bfloat16* __restrict__ Ah, const __nv_bfloat16* __restrict__ Al,
    const __nv_bfloat16* __restrict__ Bh, const __nv_bfloat16* __restrict__ Bl,
    float* __restrict__ C, int M, int N, int K)
{
    extern __shared__ __align__(128) char smem[];
    const uint32_t sb = smem_u32(smem);
    const int tid = threadIdx.x;
    const int wid = tid >> 5;
    const int lane = tid & 31;
    const int bm = blockIdx.y * 128;
    const int bn = blockIdx.x * 128;
    const int warp_m = (wid >> 2) * 64;
    const int warp_n = (wid & 3) * 32;

    const __nv_bfloat16* gp[4] = {
        Ah + (size_t)bm * K, Al + (size_t)bm * K,
        Bh + (size_t)bn * K, Bl + (size_t)bn * K };

    const int lrow0 = tid >> 2;
    const int lq = tid & 3;

    auto load_stage = [&](int c, int st) {
#pragma unroll
        for (int t = 0; t < 4; t++) {
            const __nv_bfloat16* P = gp[t] + (size_t)c * BK;
#pragma unroll
            for (int it = 0; it < 2; it++) {
                int row = lrow0 + it * 64;
                uint32_t sa = sb + GOFF(t, st) + (row * GSTRIDE + lq * 8) * 2;
                CP_ASYNC16(sa, P + (size_t)row * K + lq * 8);
            }
        }
        CP_COMMIT();
    };

    float acc[4][4][4];
#pragma unroll
    for (int i = 0; i < 4; i++)
#pragma unroll
        for (int j = 0; j < 4; j++)
#pragma unroll
            for (int r = 0; r < 4; r++) acc[i][j][r] = 0.0f;

    const int nchunk = K / BK;
    load_stage(0, 0);

    const int a_r = lane & 15;
    const int a_c = (lane >> 4) * 8;
    const int g4 = lane >> 3;
    const int b4_r = (g4 >> 1) * 8 + (lane & 7);
    const int b4_c = (g4 & 1) * 8;

    for (int c = 0; c < nchunk; c++) {
        const int st = c & 1;
        if (c + 1 < nchunk) {
            load_stage(c + 1, st ^ 1);
            CP_WAIT(1);
        } else {
            CP_WAIT(0);
        }
        __syncthreads();

        const uint32_t sAh = sb + GOFF(0, st);
        const uint32_t sAl = sb + GOFF(1, st);
        const uint32_t sBh = sb + GOFF(2, st);
        const uint32_t sBl = sb + GOFF(3, st);

#pragma unroll
        for (int kf = 0; kf < 2; kf++) {
            const int kc = kf * 16;
            uint32_t ah[4][4], al[4][4], bh[4][2], bl[4][2];
#pragma unroll
            for (int mf = 0; mf < 4; mf++) {
                uint32_t ad = ((warp_m + mf * 16 + a_r) * GSTRIDE + kc + a_c) * 2;
                ldsm4(ah[mf][0], ah[mf][1], ah[mf][2], ah[mf][3], sAh + ad);
            }
#pragma unroll
            for (int np = 0; np < 2; np++) {
                uint32_t bd = ((warp_n + np * 16 + b4_r) * GSTRIDE + kc + b4_c) * 2;
                ldsm4(bh[np * 2][0], bh[np * 2][1],
                      bh[np * 2 + 1][0], bh[np * 2 + 1][1], sBh + bd);
                ldsm4(bl[np * 2][0], bl[np * 2][1],
                      bl[np * 2 + 1][0], bl[np * 2 + 1][1], sBl + bd);
            }
#pragma unroll
            for (int mf = 0; mf < 4; mf++)
#pragma unroll
                for (int nf = 0; nf < 4; nf++) {
                    mma_bf16(acc[mf][nf], ah[mf], bh[nf]);
                    mma_bf16(acc[mf][nf], ah[mf], bl[nf]);
                }
#pragma unroll
            for (int mf = 0; mf < 4; mf++) {
                uint32_t ad = ((warp_m + mf * 16 + a_r) * GSTRIDE + kc + a_c) * 2;
                ldsm4(al[mf][0], al[mf][1], al[mf][2], al[mf][3], sAl + ad);
            }
#pragma unroll
            for (int mf = 0; mf < 4; mf++)
#pragma unroll
                for (int nf = 0; nf < 4; nf++)
                    mma_bf16(acc[mf][nf], al[mf], bh[nf]);
        }
        __syncthreads();
    }

    const int er = lane >> 2;
    const int ec = (lane & 3) * 2;
#pragma unroll
    for (int mf = 0; mf < 4; mf++) {
#pragma unroll
        for (int nf = 0; nf < 4; nf++) {
            float* base = C + (size_t)(bm + warp_m + mf * 16 + er) * N
                            + bn + warp_n + nf * 8 + ec;
            *(float2*)base = make_float2(acc[mf][nf][0], acc[mf][nf][1]);
            *(float2*)(base + 8 * N) = make_float2(acc[mf][nf][2], acc[mf][nf][3]);
        }
    }
}

// ---------------------------------------------------------------------------
// Elementwise split fp32 -> (hi, lo) bf16.
// ---------------------------------------------------------------------------
__global__ void split_kernel(const float4* __restrict__ src,
                             __nv_bfloat162* __restrict__ dh,
                             __nv_bfloat162* __restrict__ dl, int n4)
{
    int i = blockIdx.x * blockDim.x + threadIdx.x;
    if (i >= n4) return;
    float4 v = src[i];
    __nv_bfloat16 h0 = __float2bfloat16(v.x);
    __nv_bfloat16 h1 = __float2bfloat16(v.y);
    __nv_bfloat16 h2 = __float2bfloat16(v.z);
    __nv_bfloat16 h3 = __float2bfloat16(v.w);
    dh[2 * i]     = __nv_bfloat162(h0, h1);
    dh[2 * i + 1] = __nv_bfloat162(h2, h3);
    __nv_bfloat16 l0 = __float2bfloat16(v.x - __bfloat162float(h0));
    __nv_bfloat16 l1 = __float2bfloat16(v.y - __bfloat162float(h1));
    __nv_bfloat16 l2 = __float2bfloat16(v.z - __bfloat162float(h2));
    __nv_bfloat16 l3 = __float2bfloat16(v.w - __bfloat162float(h3));
    dl[2 * i]     = __nv_bfloat162(l0, l1);
    dl[2 * i + 1] = __nv_bfloat162(l2, l3);
}

// ---------------------------------------------------------------------------
// Transpose + split: src [K][N] fp32 -> dst_hi/lo [N][K] bf16.
// ---------------------------------------------------------------------------
__global__ void transpose_split_kernel(const float* __restrict__ src,
                                       __nv_bfloat16* __restrict__ dh,
                                       __nv_bfloat16* __restrict__ dl,
                                       int K, int N)
{
    __shared__ float t[32][33];
    const int k0 = blockIdx.y * 32, n0 = blockIdx.x * 32;
    const int tx = threadIdx.x, ty = threadIdx.y;
#pragma unroll
    for (int i = 0; i < 32; i += 8)
        t[ty + i][tx] = src[(size_t)(k0 + ty + i) * N + n0 + tx];
    __syncthreads();
#pragma unroll
    for (int i = 0; i < 32; i += 8) {
        float v = t[tx][ty + i];
        __nv_bfloat16 h = __float2bfloat16(v);
        float rres = v - __bfloat162float(h);
        size_t o = (size_t)(n0 + ty + i) * K + k0 + tx;
        dh[o] = h;
        dl[o] = __float2bfloat16(rres);
    }
}

// ---------------------------------------------------------------------------
// V transpose+split from fused qkv: [b][s][1536] (v at col 1280+kh*64+d)
//   -> vt_hi/lo [b][kh][d][s] bf16.
// ---------------------------------------------------------------------------
__global__ void vtrans_split_kernel(const float* __restrict__ qkv,
                                    __nv_bfloat16* __restrict__ dh,
                                    __nv_bfloat16* __restrict__ dl)
{
    __shared__ float t[32][33];
    const int s0 = blockIdx.x * 32;
    const int d0 = blockIdx.y * 32;
    const int bk = blockIdx.z;
    const int b = bk / NKH, khead = bk % NKH;
    const int tx = threadIdx.x, ty = threadIdx.y;
#pragma unroll
    for (int i = 0; i < 32; i += 8)
        t[ty + i][tx] = qkv[(size_t)(b * SS + s0 + ty + i) * NQKV
                            + 1280 + khead * HD + d0 + tx];
    __syncthreads();
#pragma unroll
    for (int i = 0; i < 32; i += 8) {
        float val = t[tx][ty + i];
        __nv_bfloat16 h = __float2bfloat16(val);
        float rres = val - __bfloat162float(h);
        size_t o = ((size_t)(b * NKH + khead) * HD + d0 + ty + i) * SS + s0 + tx;
        dh[o] = h;
        dl[o] = __float2bfloat16(rres);
    }
}

// ---------------------------------------------------------------------------
// RoPE + split from fused qkv (row stride NQKV, column offset coff).
// Vectorized: each thread handles 4+4 d values.
// ---------------------------------------------------------------------------
__global__ void rope_split_kernel(const float* __restrict__ qkv,
                                  const float* __restrict__ cosb,
                                  const float* __restrict__ sinb,
                                  __nv_bfloat16* __restrict__ th,
                                  __nv_bfloat16* __restrict__ tl,
                                  int nheads, int coff)
{
    int idx = blockIdx.x * blockDim.x + threadIdx.x;
    int total = BB * SS * nheads * 8;
    if (idx >= total) return;
    int d4 = (idx & 7) * 4;          // 0,4,...,28
    int rest = idx >> 3;
    int hh = rest % nheads;
    int bs = rest / nheads;
    int s = bs & (SS - 1);

    const float* src = qkv + (size_t)bs * NQKV + coff + hh * HD;
    float4 v0 = *(const float4*)(src + d4);
    float4 v1 = *(const float4*)(src + d4 + 32);
    float4 c0 = *(const float4*)(cosb + s * HD + d4);
    float4 c1 = *(const float4*)(cosb + s * HD + d4 + 32);
    float4 s0 = *(const float4*)(sinb + s * HD + d4);
    float4 s1 = *(const float4*)(sinb + s * HD + d4 + 32);

    float r0x = v0.x * c0.x - v1.x * s0.x;
    float r0y = v0.y * c0.y - v1.y * s0.y;
    float r0z = v0.z * c0.z - v1.z * s0.z;
    float r0w = v0.w * c0.w - v1.w * s0.w;
    float r1x = v1.x * c1.x + v0.x * s1.x;
    float r1y = v1.y * c1.y + v0.y * s1.y;
    float r1z = v1.z * c1.z + v0.z * s1.z;
    float r1w = v1.w * c1.w + v0.w * s1.w;

    size_t base = (size_t)bs * nheads * HD + (size_t)hh * HD;

    __nv_bfloat162 h0a = __float22bfloat162_rn(make_float2(r0x, r0y));
    __nv_bfloat162 h0b = __float22bfloat162_rn(make_float2(r0z, r0w));
    __nv_bfloat162 h1a = __float22bfloat162_rn(make_float2(r1x, r1y));
    __nv_bfloat162 h1b = __float22bfloat162_rn(make_float2(r1z, r1w));
    *(uint2*)(th + base + d4)      = make_uint2(*(uint32_t*)&h0a, *(uint32_t*)&h0b);
    *(uint2*)(th + base + d4 + 32) = make_uint2(*(uint32_t*)&h1a, *(uint32_t*)&h1b);

    __nv_bfloat162 l0a = __float22bfloat162_rn(make_float2(
        r0x - __bfloat162float(h0a.x), r0y - __bfloat162float(h0a.y)));
    __nv_bfloat162 l0b = __float22bfloat162_rn(make_float2(
        r0z - __bfloat162float(h0b.x), r0w - __bfloat162float(h0b.y)));
    __nv_bfloat162 l1a = __float22bfloat162_rn(make_float2(
        r1x - __bfloat162float(h1a.x), r1y - __bfloat162float(h1a.y)));
    __nv_bfloat162 l1b = __float22bfloat162_rn(make_float2(
        r1z - __bfloat162float(h1b.x), r1w - __bfloat162float(h1b.y)));
    *(uint2*)(tl + base + d4)      = make_uint2(*(uint32_t*)&l0a, *(uint32_t*)&l0b);
    *(uint2*)(tl + base + d4 + 32) = make_uint2(*(uint32_t*)&l1a, *(uint32_t*)&l1b);
}

// ---------------------------------------------------------------------------
// HMMA bf16x3 flash attention, causal, GQA.
// BLOCK_M=128 (8 warps), BLOCK_N=64; ldsm4 B-fragments; LPT (reversed qt).
// ---------------------------------------------------------------------------
#define FSTR 72
#define FTILE64 (64 * FSTR * 2)
#define FQ_TILE (128 * FSTR * 2)
#define FQ_H 0
#define FQ_L FQ_TILE
#define FSTG(st) (2 * FQ_TILE + (st) * 4 * FTILE64)
#define FLASH_SMEM (2 * FQ_TILE + 2 * 4 * FTILE64)   // 110592 B

__global__ __launch_bounds__(256) void flash_hmma_kernel(
    const __nv_bfloat16* __restrict__ Qh, const __nv_bfloat16* __restrict__ Ql,
    const __nv_bfloat16* __restrict__ Kh, const __nv_bfloat16* __restrict__ Kl,
    const __nv_bfloat16* __restrict__ Vth, const __nv_bfloat16* __restrict__ Vtl,
    __nv_bfloat16* __restrict__ Oh, __nv_bfloat16* __restrict__ Ol)
{
    extern __shared__ __align__(128) char smem[];
    const uint32_t sb = smem_u32(smem);
    const int tid = threadIdx.x;
    const int wid = tid >> 5;
    const int lane = tid & 31;
    const int qt = gridDim.x - 1 - blockIdx.x;   // LPT: heavy tiles first
    const int h  = blockIdx.y;
    const int b  = blockIdx.z;
    const int q0 = qt * 128;
    const int khead = h >> 2;
    const int warp_m = wid * 16;

    const int er = lane >> 2;
    const int ec = (lane & 3) * 2;
    const int a_r = lane & 15;
    const int a_c = (lane >> 4) * 8;
    const int g4 = lane >> 3;
    const int b4_r = (g4 >> 1) * 8 + (lane & 7);
    const int b4_c = (g4 & 1) * 8;

    const __nv_bfloat16* qh_g = Qh + ((size_t)(b * SS + q0) * NH + h) * HD;
    const __nv_bfloat16* ql_g = Ql + ((size_t)(b * SS + q0) * NH + h) * HD;
    const __nv_bfloat16* kh_g = Kh + ((size_t)b * SS * NKH + khead) * HD;
    const __nv_bfloat16* kl_g = Kl + ((size_t)b * SS * NKH + khead) * HD;
    const __nv_bfloat16* vth_g = Vth + (size_t)(b * NKH + khead) * HD * SS;
    const __nv_bfloat16* vtl_g = Vtl + (size_t)(b * NKH + khead) * HD * SS;

    auto load_tile64 = [&](const __nv_bfloat16* g, size_t rstride, uint32_t sofs) {
#pragma unroll
        for (int it = 0; it < 2; it++) {
            int ch = tid + it * 256;
            int r = ch >> 3;
            int q8 = ch & 7;
            CP_ASYNC16(sb + sofs + (r * FSTR + q8 * 8) * 2,
                       g + (size_t)r * rstride + q8 * 8);
        }
    };
    auto load_q = [&](const __nv_bfloat16* g, uint32_t sofs) {
#pragma unroll
        for (int it = 0; it < 4; it++) {
            int ch = tid + it * 256;
            int r = ch >> 3;
            int q8 = ch & 7;
            CP_ASYNC16(sb + sofs + (r * FSTR + q8 * 8) * 2,
                       g + (size_t)r * (NH * HD) + q8 * 8);
        }
    };

    load_q(qh_g, FQ_H);
    load_q(ql_g, FQ_L);
    load_tile64(kh_g, NKH * HD, FSTG(0) + 0 * FTILE64);
    load_tile64(kl_g, NKH * HD, FSTG(0) + 1 * FTILE64);
    load_tile64(vth_g, SS, FSTG(0) + 2 * FTILE64);
    load_tile64(vtl_g, SS, FSTG(0) + 3 * FTILE64);
    CP_COMMIT();

    float m[2] = {-1e30f, -1e30f};
    float l[2] = {0.0f, 0.0f};
    float acc[8][4];
#pragma unroll
    for (int i = 0; i < 8; i++)
#pragma unroll
        for (int r = 0; r < 4; r++) acc[i][r] = 0.0f;

    const int kt_end = 2 * qt + 1;

    for (int kt = 0; kt <= kt_end; kt++) {
        const int st = kt & 1;
        if (kt < kt_end) {
            const int kn = (kt + 1) * 64;
            load_tile64(kh_g + (size_t)kn * NKH * HD, NKH * HD, FSTG(st ^ 1) + 0 * FTILE64);
            load_tile64(kl_g + (size_t)kn * NKH * HD, NKH * HD, FSTG(st ^ 1) + 1 * FTILE64);
            load_tile64(vth_g + kn, SS, FSTG(st ^ 1) + 2 * FTILE64);
            load_tile64(vtl_g + kn, SS, FSTG(st ^ 1) + 3 * FTILE64);
            CP_COMMIT();
            CP_WAIT(1);
        } else {
            CP_WAIT(0);
        }
        __syncthreads();

        const int row_lo = q0 + warp_m;
        const bool any  = (kt * 64     <= row_lo + 15);
        const bool full = (kt * 64 + 63 <= row_lo);

        if (any) {
            const uint32_t sKh = sb + FSTG(st) + 0 * FTILE64;
            const uint32_t sKl = sb + FSTG(st) + 1 * FTILE64;
            const uint32_t sVh = sb + FSTG(st) + 2 * FTILE64;
            const uint32_t sVl = sb + FSTG(st) + 3 * FTILE64;

            float sf[8][4];
#pragma unroll
            for (int nf = 0; nf < 8; nf++)
#pragma unroll
                for (int r = 0; r < 4; r++) sf[nf][r] = 0.0f;

#pragma unroll
            for (int kf = 0; kf < 4; kf++) {
                const int kc = kf * 16;
                uint32_t qah[4], qal[4];
                uint32_t ad = ((warp_m + a_r) * FSTR + kc + a_c) * 2;
                ldsm4(qah[0], qah[1], qah[2], qah[3], sb + FQ_H + ad);
                ldsm4(qal[0], qal[1], qal[2], qal[3], sb + FQ_L + ad);
#pragma unroll
                for (int np = 0; np < 4; np++) {
                    uint32_t bd = ((np * 16 + b4_r) * FSTR + kc + b4_c) * 2;
                    uint32_t kbh[4], kbl[4];
                    ldsm4(kbh[0], kbh[1], kbh[2], kbh[3], sKh + bd);
                    ldsm4(kbl[0], kbl[1], kbl[2], kbl[3], sKl + bd);
                    mma_bf16(sf[np * 2],     qah, kbh);
                    mma_bf16(sf[np * 2],     qah, kbl);
                    mma_bf16(sf[np * 2],     qal, kbh);
                    mma_bf16(sf[np * 2 + 1], qah, kbh + 2);
                    mma_bf16(sf[np * 2 + 1], qah, kbl + 2);
                    mma_bf16(sf[np * 2 + 1], qal, kbh + 2);
                }
            }

            const float sc = 0.125f;
            if (!full) {
                const int i0 = row_lo + er;
#pragma unroll
                for (int nf = 0; nf < 8; nf++) {
                    int j0 = kt * 64 + nf * 8 + ec;
                    sf[nf][0] = (j0     <= i0)     ? sf[nf][0] * sc : -1e30f;
                    sf[nf][1] = (j0 + 1 <= i0)     ? sf[nf][1] * sc : -1e30f;
                    sf[nf][2] = (j0     <= i0 + 8) ? sf[nf][2] * sc : -1e30f;
                    sf[nf][3] = (j0 + 1 <= i0 + 8) ? sf[nf][3] * sc : -1e30f;
                }
            } else {
#pragma unroll
                for (int nf = 0; nf < 8; nf++)
#pragma unroll
                    for (int r = 0; r < 4; r++) sf[nf][r] *= sc;
            }

            float rmax0 = -1e30f, rmax1 = -1e30f;
#pragma unroll
            for (int nf = 0; nf < 8; nf++) {
                rmax0 = fmaxf(rmax0, fmaxf(sf[nf][0], sf[nf][1]));
                rmax1 = fmaxf(rmax1, fmaxf(sf[nf][2], sf[nf][3]));
            }
            rmax0 = fmaxf(rmax0, __shfl_xor_sync(0xffffffffu, rmax0, 1));
            rmax0 = fmaxf(rmax0, __shfl_xor_sync(0xffffffffu, rmax0, 2));
            rmax1 = fmaxf(rmax1, __shfl_xor_sync(0xffffffffu, rmax1, 1));
            rmax1 = fmaxf(rmax1, __shfl_xor_sync(0xffffffffu, rmax1, 2));

            float nm0 = fmaxf(m[0], rmax0), nm1 = fmaxf(m[1], rmax1);
            float al0 = __expf(m[0] - nm0), al1 = __expf(m[1] - nm1);
            m[0] = nm0; m[1] = nm1;

            float sum0 = 0.0f, sum1 = 0.0f;
#pragma unroll
            for (int nf = 0; nf < 8; nf++) {
                sf[nf][0] = __expf(sf[nf][0] - nm0);
                sf[nf][1] = __expf(sf[nf][1] - nm0);
                sf[nf][2] = __expf(sf[nf][2] - nm1);
                sf[nf][3] = __expf(sf[nf][3] - nm1);
                sum0 += sf[nf][0] + sf[nf][1];
                sum1 += sf[nf][2] + sf[nf][3];
            }
            sum0 += __shfl_xor_sync(0xffffffffu, sum0, 1);
            sum0 += __shfl_xor_sync(0xffffffffu, sum0, 2);
            sum1 += __shfl_xor_sync(0xffffffffu, sum1, 1);
            sum1 += __shfl_xor_sync(0xffffffffu, sum1, 2);
            l[0] = l[0] * al0 + sum0;
            l[1] = l[1] * al1 + sum1;
#pragma unroll
            for (int i = 0; i < 8; i++) {
                acc[i][0] *= al0; acc[i][1] *= al0;
                acc[i][2] *= al1; acc[i][3] *= al1;
            }

            uint32_t pha[4][4], pla[4][4];
#pragma unroll
            for (int kf = 0; kf < 4; kf++) {
#pragma unroll
                for (int half = 0; half < 2; half++) {
                    const float* s2 = sf[kf * 2 + half];
                    __nv_bfloat162 h01 = __float22bfloat162_rn(make_float2(s2[0], s2[1]));
                    __nv_bfloat162 h23 = __float22bfloat162_rn(make_float2(s2[2], s2[3]));
                    __nv_bfloat162 l01 = __float22bfloat162_rn(make_float2(
                        s2[0] - __bfloat162float(h01.x), s2[1] - __bfloat162float(h01.y)));
                    __nv_bfloat162 l23 = __float22bfloat162_rn(make_float2(
                        s2[2] - __bfloat162float(h23.x), s2[3] - __bfloat162float(h23.y)));
                    pha[kf][half * 2 + 0] = *(uint32_t*)&h01;
                    pha[kf][half * 2 + 1] = *(uint32_t*)&h23;
                    pla[kf][half * 2 + 0] = *(uint32_t*)&l01;
                    pla[kf][half * 2 + 1] = *(uint32_t*)&l23;
                }
            }

#pragma unroll
            for (int kf = 0; kf < 4; kf++) {
#pragma unroll
                for (int np = 0; np < 4; np++) {
                    uint32_t bd = ((np * 16 + b4_r) * FSTR + kf * 16 + b4_c) * 2;
                    uint32_t vbh[4], vbl[4];
                    ldsm4(vbh[0], vbh[1], vbh[2], vbh[3], sVh + bd);
                    ldsm4(vbl[0], vbl[1], vbl[2], vbl[3], sVl + bd);
                    mma_bf16(acc[np * 2],     pha[kf], vbh);
                    mma_bf16(acc[np * 2],     pha[kf], vbl);
                    mma_bf16(acc[np * 2],     pla[kf], vbh);
                    mma_bf16(acc[np * 2 + 1], pha[kf], vbh + 2);
                    mma_bf16(acc[np * 2 + 1], pha[kf], vbl + 2);
                    mma_bf16(acc[np * 2 + 1], pla[kf], vbh + 2);
                }
            }
        }
        __syncthreads();
    }

    float inv0 = 1.0f / l[0], inv1 = 1.0f / l[1];
#pragma unroll
    for (int nf = 0; nf < 8; nf++) {
        size_t o0 = ((size_t)(b * SS + q0 + warp_m + er) * NH + h) * HD + nf * 8 + ec;
        size_t o1 = ((size_t)(b * SS + q0 + warp_m + er + 8) * NH + h) * HD + nf * 8 + ec;
        float v00 = acc[nf][0] * inv0, v01 = acc[nf][1] * inv0;
        float v10 = acc[nf][2] * inv1, v11 = acc[nf][3] * inv1;
        __nv_bfloat162 h0 = __float22bfloat162_rn(make_float2(v00, v01));
        __nv_bfloat162 h1 = __float22bfloat162_rn(make_float2(v10, v11));
        __nv_bfloat162 l0 = __float22bfloat162_rn(make_float2(
            v00 - __bfloat162float(h0.x), v01 - __bfloat162float(h0.y)));
        __nv_bfloat162 l1 = __float22bfloat162_rn(make_float2(
            v10 - __bfloat162float(h1.x), v11 - __bfloat162float(h1.y)));
        *(uint32_t*)(Oh + o0) = *(uint32_t*)&h0;
        *(uint32_t*)(Oh + o1) = *(uint32_t*)&h1;
        *(uint32_t*)(Ol + o0) = *(uint32_t*)&l0;
        *(uint32_t*)(Ol + o1) = *(uint32_t*)&l1;
    }
}

// ---------------------------------------------------------------------------
extern "C" void kernel_launch(void* const* d_in, const int* in_sizes, int n_in,
                              void* d_out, int out_size)
{
    const float* x    = (const float*)d_in[0];
    const float* cosb = (const float*)d_in[1];
    const float* sinb = (const float*)d_in[2];
    const float* wq   = (const float*)d_in[3];
    const float* wk   = (const float*)d_in[4];
    const float* wv   = (const float*)d_in[5];
    const float* wo   = (const float*)d_in[6];
    float* out = (float*)d_out;

    float* qkv;
    cudaGetSymbolAddress((void**)&qkv, g_qkv);

    __nv_bfloat16 *xh, *xl, *oh, *ol;
    __nv_bfloat16 *wqkvh, *wqkvl, *woh, *wol;
    __nv_bfloat16 *qh, *ql, *kh2, *kl2, *vth, *vtl;
    cudaGetSymbolAddress((void**)&xh, g_xh);
    cudaGetSymbolAddress((void**)&xl, g_xl);
    cudaGetSymbolAddress((void**)&oh, g_oh);
    cudaGetSymbolAddress((void**)&ol, g_ol);
    cudaGetSymbolAddress((void**)&wqkvh, g_wqkvh);
    cudaGetSymbolAddress((void**)&wqkvl, g_wqkvl);
    cudaGetSymbolAddress((void**)&woh, g_woh);
    cudaGetSymbolAddress((void**)&wol, g_wol);
    cudaGetSymbolAddress((void**)&qh, g_qh);
    cudaGetSymbolAddress((void**)&ql, g_ql);
    cudaGetSymbolAddress((void**)&kh2, g_kh2);
    cudaGetSymbolAddress((void**)&kl2, g_kl2);
    cudaGetSymbolAddress((void**)&vth, g_vth);
    cudaGetSymbolAddress((void**)&vtl, g_vtl);

    cudaFuncSetAttribute(gemm_bf16x3_kernel,
                         cudaFuncAttributeMaxDynamicSharedMemorySize, GEMM_SMEM);
    cudaFuncSetAttribute(flash_hmma_kernel,
                         cudaFuncAttributeMaxDynamicSharedMemorySize, FLASH_SMEM);

    const int M = BB * SS;  // 4096

    // Split activations; transpose+split weights into fused wqkv + wo
    {
        int n4 = M * DMODEL / 4;
        split_kernel<<<(n4 + 255) / 256, 256>>>(
            (const float4*)x, (__nv_bfloat162*)xh, (__nv_bfloat162*)xl, n4);
        dim3 blk(32, 8);
        transpose_split_kernel<<<dim3((NH * HD) / 32, DMODEL / 32), blk>>>(
            wq, wqkvh, wqkvl, DMODEL, NH * HD);
        transpose_split_kernel<<<dim3((NKH * HD) / 32, DMODEL / 32), blk>>>(
            wk, wqkvh + 1024 * DMODEL, wqkvl + 1024 * DMODEL, DMODEL, NKH * HD);
        transpose_split_kernel<<<dim3((NKH * HD) / 32, DMODEL / 32), blk>>>(
            wv, wqkvh + 1280 * DMODEL, wqkvl + 1280 * DMODEL, DMODEL, NKH * HD);
        transpose_split_kernel<<<dim3(DMODEL / 32, (NH * HD) / 32), blk>>>(
            wo, woh, wol, NH * HD, DMODEL);
    }

    // Fused QKV projection (HMMA bf16x3): [4096][1536]
    gemm_bf16x3_kernel<<<dim3(NQKV / 128, M / 128), 256, GEMM_SMEM>>>(
        xh, xl, wqkvh, wqkvl, qkv, M, NQKV, DMODEL);

    // RoPE + split (q, k from fused buffer); V transpose + split
    {
        int nq = BB * SS * NH * 8;
        rope_split_kernel<<<(nq + 255) / 256, 256>>>(qkv, cosb, sinb, qh, ql, NH, 0);
        int nk = BB * SS * NKH * 8;
        rope_split_kernel<<<(nk + 255) / 256, 256>>>(qkv, cosb, sinb, kh2, kl2, NKH, 1024);
        dim3 blk(32, 8);
        vtrans_split_kernel<<<dim3(SS / 32, HD / 32, BB * NKH), blk>>>(qkv, vth, vtl);
    }

    // Causal GQA flash attention (HMMA bf16x3)
    flash_hmma_kernel<<<dim3(SS / 128, NH, BB), 256, FLASH_SMEM>>>(
        qh, ql, kh2, kl2, vth, vtl, oh, ol);

    // Output projection (HMMA bf16x3)
    gemm_bf16x3_kernel<<<dim3(DMODEL / 128, M / 128), 256, GEMM_SMEM>>>(
        oh, ol, woh, wol, out, M, DMODEL, DMODEL);
}

// round 7
// speedup vs baseline: 3.1378x; 1.0130x over previous
#include <cuda_runtime.h>
#include <cuda_bf16.h>
#include <cstdint>
#include <math.h>

#define BB 2
#define SS 2048
#define DMODEL 1024
#define NH 16
#define NKH 4
#define HD 64
#define NQKV 1536   // NH*HD + NKH*HD + NKH*HD

// ---------------------------------------------------------------------------
// Scratch (device globals: allocation-free)
// ---------------------------------------------------------------------------
__device__ float g_qkv[BB * SS * NQKV];               // fused q|k|v fp32

__device__ __nv_bfloat16 g_xh[BB * SS * DMODEL];
__device__ __nv_bfloat16 g_xl[BB * SS * DMODEL];
__device__ __nv_bfloat16 g_oh[BB * SS * NH * HD];
__device__ __nv_bfloat16 g_ol[BB * SS * NH * HD];
__device__ __nv_bfloat16 g_wqkvh[NQKV * DMODEL];      // wq|wk|wv rows, [N][K]
__device__ __nv_bfloat16 g_wqkvl[NQKV * DMODEL];
__device__ __nv_bfloat16 g_woh[DMODEL * (NH * HD)];
__device__ __nv_bfloat16 g_wol[DMODEL * (NH * HD)];

__device__ __nv_bfloat16 g_qh[BB * SS * NH * HD];
__device__ __nv_bfloat16 g_ql[BB * SS * NH * HD];
__device__ __nv_bfloat16 g_kh2[BB * SS * NKH * HD];
__device__ __nv_bfloat16 g_kl2[BB * SS * NKH * HD];
__device__ __nv_bfloat16 g_vth[BB * NKH * HD * SS];   // [b][kh][d][s]
__device__ __nv_bfloat16 g_vtl[BB * NKH * HD * SS];

// ---------------------------------------------------------------------------
// Warp-level MMA helpers
// ---------------------------------------------------------------------------
__device__ __forceinline__ uint32_t smem_u32(const void* p) {
    uint32_t a;
    asm("{ .reg .u64 t; cvta.to.shared.u64 t, %1; cvt.u32.u64 %0, t; }"
        : "=r"(a) : "l"(p));
    return a;
}

__device__ __forceinline__ void ldsm4(uint32_t& r0, uint32_t& r1,
                                      uint32_t& r2, uint32_t& r3, uint32_t a) {
    asm volatile("ldmatrix.sync.aligned.m8n8.x4.shared.b16 {%0,%1,%2,%3}, [%4];"
                 : "=r"(r0), "=r"(r1), "=r"(r2), "=r"(r3) : "r"(a));
}

__device__ __forceinline__ void mma_bf16(float* c, const uint32_t* a,
                                         const uint32_t* b) {
    asm volatile(
        "mma.sync.aligned.m16n8k16.row.col.f32.bf16.bf16.f32 "
        "{%0,%1,%2,%3}, {%4,%5,%6,%7}, {%8,%9}, {%0,%1,%2,%3};"
        : "+f"(c[0]), "+f"(c[1]), "+f"(c[2]), "+f"(c[3])
        : "r"(a[0]), "r"(a[1]), "r"(a[2]), "r"(a[3]), "r"(b[0]), "r"(b[1]));
}

#define CP_ASYNC16(sa, ga) \
    asm volatile("cp.async.cg.shared.global [%0], [%1], 16;" \
                 :: "r"(sa), "l"(ga))
#define CP_COMMIT() asm volatile("cp.async.commit_group;")
#define CP_WAIT(N)  asm volatile("cp.async.wait_group %0;" :: "n"(N))

// ---------------------------------------------------------------------------
// bf16x3 HMMA GEMM: C[M,N] = A[M,K] @ B[N,K]^T.
// 128x128 CTA tile, BK=32, 8 warps (2x4), ldsm4 A+B fragments, 2-stage,
// 2 CTAs/SM for cross-CTA latency hiding.
// ---------------------------------------------------------------------------
#define BK 32
#define GSTRIDE 40
#define GTILE_B (128 * GSTRIDE * 2)
#define GOFF(t, st) (((st) * 4 + (t)) * GTILE_B)
#define GEMM_SMEM (8 * GTILE_B)

__global__ __launch_bounds__(256, 2) void gemm_bf16x3_kernel(
    const __nv_bfloat16* __restrict__ Ah, const __nv_bfloat16* __restrict__ Al,
    const __nv_bfloat16* __restrict__ Bh, const __nv_bfloat16* __restrict__ Bl,
    float* __restrict__ C, int M, int N, int K)
{
    extern __shared__ __align__(128) char smem[];
    const uint32_t sb = smem_u32(smem);
    const int tid = threadIdx.x;
    const int wid = tid >> 5;
    const int lane = tid & 31;
    const int bm = blockIdx.y * 128;
    const int bn = blockIdx.x * 128;
    const int warp_m = (wid >> 2) * 64;
    const int warp_n = (wid & 3) * 32;

    const __nv_bfloat16* gp[4] = {
        Ah + (size_t)bm * K, Al + (size_t)bm * K,
        Bh + (size_t)bn * K, Bl + (size_t)bn * K };

    const int lrow0 = tid >> 2;
    const int lq = tid & 3;

    auto load_stage = [&](int c, int st) {
#pragma unroll
        for (int t = 0; t < 4; t++) {
            const __nv_bfloat16* P = gp[t] + (size_t)c * BK;
#pragma unroll
            for (int it = 0; it < 2; it++) {
                int row = lrow0 + it * 64;
                uint32_t sa = sb + GOFF(t, st) + (row * GSTRIDE + lq * 8) * 2;
                CP_ASYNC16(sa, P + (size_t)row * K + lq * 8);
            }
        }
        CP_COMMIT();
    };

    float acc[4][4][4];
#pragma unroll
    for (int i = 0; i < 4; i++)
#pragma unroll
        for (int j = 0; j < 4; j++)
#pragma unroll
            for (int r = 0; r < 4; r++) acc[i][j][r] = 0.0f;

    const int nchunk = K / BK;
    load_stage(0, 0);

    const int a_r = lane & 15;
    const int a_c = (lane >> 4) * 8;
    const int g4 = lane >> 3;
    const int b4_r = (g4 >> 1) * 8 + (lane & 7);
    const int b4_c = (g4 & 1) * 8;

    for (int c = 0; c < nchunk; c++) {
        const int st = c & 1;
        if (c + 1 < nchunk) {
            load_stage(c + 1, st ^ 1);
            CP_WAIT(1);
        } else {
            CP_WAIT(0);
        }
        __syncthreads();

        const uint32_t sAh = sb + GOFF(0, st);
        const uint32_t sAl = sb + GOFF(1, st);
        const uint32_t sBh = sb + GOFF(2, st);
        const uint32_t sBl = sb + GOFF(3, st);

#pragma unroll
        for (int kf = 0; kf < 2; kf++) {
            const int kc = kf * 16;
            uint32_t ah[4][4], al[4][4], bh[4][2], bl[4][2];
#pragma unroll
            for (int mf = 0; mf < 4; mf++) {
                uint32_t ad = ((warp_m + mf * 16 + a_r) * GSTRIDE + kc + a_c) * 2;
                ldsm4(ah[mf][0], ah[mf][1], ah[mf][2], ah[mf][3], sAh + ad);
            }
#pragma unroll
            for (int np = 0; np < 2; np++) {
                uint32_t bd = ((warp_n + np * 16 + b4_r) * GSTRIDE + kc + b4_c) * 2;
                ldsm4(bh[np * 2][0], bh[np * 2][1],
                      bh[np * 2 + 1][0], bh[np * 2 + 1][1], sBh + bd);
                ldsm4(bl[np * 2][0], bl[np * 2][1],
                      bl[np * 2 + 1][0], bl[np * 2 + 1][1], sBl + bd);
            }
#pragma unroll
            for (int mf = 0; mf < 4; mf++)
#pragma unroll
                for (int nf = 0; nf < 4; nf++) {
                    mma_bf16(acc[mf][nf], ah[mf], bh[nf]);
                    mma_bf16(acc[mf][nf], ah[mf], bl[nf]);
                }
#pragma unroll
            for (int mf = 0; mf < 4; mf++) {
                uint32_t ad = ((warp_m + mf * 16 + a_r) * GSTRIDE + kc + a_c) * 2;
                ldsm4(al[mf][0], al[mf][1], al[mf][2], al[mf][3], sAl + ad);
            }
#pragma unroll
            for (int mf = 0; mf < 4; mf++)
#pragma unroll
                for (int nf = 0; nf < 4; nf++)
                    mma_bf16(acc[mf][nf], al[mf], bh[nf]);
        }
        __syncthreads();
    }

    const int er = lane >> 2;
    const int ec = (lane & 3) * 2;
#pragma unroll
    for (int mf = 0; mf < 4; mf++) {
#pragma unroll
        for (int nf = 0; nf < 4; nf++) {
            float* base = C + (size_t)(bm + warp_m + mf * 16 + er) * N
                            + bn + warp_n + nf * 8 + ec;
            *(float2*)base = make_float2(acc[mf][nf][0], acc[mf][nf][1]);
            *(float2*)(base + 8 * N) = make_float2(acc[mf][nf][2], acc[mf][nf][3]);
        }
    }
}

// ---------------------------------------------------------------------------
// Elementwise split fp32 -> (hi, lo) bf16.
// ---------------------------------------------------------------------------
__global__ void split_kernel(const float4* __restrict__ src,
                             __nv_bfloat162* __restrict__ dh,
                             __nv_bfloat162* __restrict__ dl, int n4)
{
    int i = blockIdx.x * blockDim.x + threadIdx.x;
    if (i >= n4) return;
    float4 v = src[i];
    __nv_bfloat16 h0 = __float2bfloat16(v.x);
    __nv_bfloat16 h1 = __float2bfloat16(v.y);
    __nv_bfloat16 h2 = __float2bfloat16(v.z);
    __nv_bfloat16 h3 = __float2bfloat16(v.w);
    dh[2 * i]     = __nv_bfloat162(h0, h1);
    dh[2 * i + 1] = __nv_bfloat162(h2, h3);
    __nv_bfloat16 l0 = __float2bfloat16(v.x - __bfloat162float(h0));
    __nv_bfloat16 l1 = __float2bfloat16(v.y - __bfloat162float(h1));
    __nv_bfloat16 l2 = __float2bfloat16(v.z - __bfloat162float(h2));
    __nv_bfloat16 l3 = __float2bfloat16(v.w - __bfloat162float(h3));
    dl[2 * i]     = __nv_bfloat162(l0, l1);
    dl[2 * i + 1] = __nv_bfloat162(l2, l3);
}

// ---------------------------------------------------------------------------
// Fused weight prep: all 4 transpose+splits in one launch.
// Segments of 32x32 tiles: [0,1024) wq, [1024,1280) wk, [1280,1536) wv,
// [1536,2560) wo.
// ---------------------------------------------------------------------------
__global__ void weight_prep_kernel(
    const float* __restrict__ wq, const float* __restrict__ wk,
    const float* __restrict__ wv, const float* __restrict__ wo,
    __nv_bfloat16* __restrict__ wqkvh, __nv_bfloat16* __restrict__ wqkvl,
    __nv_bfloat16* __restrict__ woh, __nv_bfloat16* __restrict__ wol)
{
    __shared__ float t[32][33];
    const int tile = blockIdx.x;
    const float* src;
    __nv_bfloat16 *dh, *dl;
    int N, tloc;
    if (tile < 1024)      { src = wq; dh = wqkvh;                  dl = wqkvl;                  N = 1024; tloc = tile; }
    else if (tile < 1280) { src = wk; dh = wqkvh + 1024 * DMODEL;  dl = wqkvl + 1024 * DMODEL;  N = 256;  tloc = tile - 1024; }
    else if (tile < 1536) { src = wv; dh = wqkvh + 1280 * DMODEL;  dl = wqkvl + 1280 * DMODEL;  N = 256;  tloc = tile - 1280; }
    else                  { src = wo; dh = woh;                    dl = wol;                    N = 1024; tloc = tile - 1536; }
    const int nx = N >> 5;
    const int K = 1024;                 // all weights have 1024 src rows
    const int n0 = (tloc % nx) * 32;
    const int k0 = (tloc / nx) * 32;
    const int tx = threadIdx.x, ty = threadIdx.y;   // 32 x 8
#pragma unroll
    for (int i = 0; i < 32; i += 8)
        t[ty + i][tx] = src[(size_t)(k0 + ty + i) * N + n0 + tx];
    __syncthreads();
#pragma unroll
    for (int i = 0; i < 32; i += 8) {
        float v = t[tx][ty + i];
        __nv_bfloat16 h = __float2bfloat16(v);
        float rres = v - __bfloat162float(h);
        size_t o = (size_t)(n0 + ty + i) * K + k0 + tx;
        dh[o] = h;
        dl[o] = __float2bfloat16(rres);
    }
}

// ---------------------------------------------------------------------------
// V transpose+split from fused qkv: [b][s][1536] -> vt_hi/lo [b][kh][d][s].
// ---------------------------------------------------------------------------
__global__ void vtrans_split_kernel(const float* __restrict__ qkv,
                                    __nv_bfloat16* __restrict__ dh,
                                    __nv_bfloat16* __restrict__ dl)
{
    __shared__ float t[32][33];
    const int s0 = blockIdx.x * 32;
    const int d0 = blockIdx.y * 32;
    const int bk = blockIdx.z;
    const int b = bk / NKH, khead = bk % NKH;
    const int tx = threadIdx.x, ty = threadIdx.y;
#pragma unroll
    for (int i = 0; i < 32; i += 8)
        t[ty + i][tx] = qkv[(size_t)(b * SS + s0 + ty + i) * NQKV
                            + 1280 + khead * HD + d0 + tx];
    __syncthreads();
#pragma unroll
    for (int i = 0; i < 32; i += 8) {
        float val = t[tx][ty + i];
        __nv_bfloat16 h = __float2bfloat16(val);
        float rres = val - __bfloat162float(h);
        size_t o = ((size_t)(b * NKH + khead) * HD + d0 + ty + i) * SS + s0 + tx;
        dh[o] = h;
        dl[o] = __float2bfloat16(rres);
    }
}

// ---------------------------------------------------------------------------
// Fused RoPE + split for q AND k from fused qkv buffer.
// idx < nq handles q (coff 0, NH heads); else k (coff 1024, NKH heads).
// ---------------------------------------------------------------------------
__global__ void rope_split_qk_kernel(const float* __restrict__ qkv,
                                     const float* __restrict__ cosb,
                                     const float* __restrict__ sinb,
                                     __nv_bfloat16* __restrict__ qh,
                                     __nv_bfloat16* __restrict__ ql,
                                     __nv_bfloat16* __restrict__ kh,
                                     __nv_bfloat16* __restrict__ kl)
{
    const int nq = BB * SS * NH * 8;
    const int nk = BB * SS * NKH * 8;
    int idx = blockIdx.x * blockDim.x + threadIdx.x;
    if (idx >= nq + nk) return;

    int nheads, coff;
    __nv_bfloat16 *th, *tl;
    if (idx < nq) { nheads = NH;  coff = 0;    th = qh; tl = ql; }
    else          { nheads = NKH; coff = 1024; th = kh; tl = kl; idx -= nq; }

    int d4 = (idx & 7) * 4;
    int rest = idx >> 3;
    int hh = rest % nheads;
    int bs = rest / nheads;
    int s = bs & (SS - 1);

    const float* src = qkv + (size_t)bs * NQKV + coff + hh * HD;
    float4 v0 = *(const float4*)(src + d4);
    float4 v1 = *(const float4*)(src + d4 + 32);
    float4 c0 = *(const float4*)(cosb + s * HD + d4);
    float4 c1 = *(const float4*)(cosb + s * HD + d4 + 32);
    float4 s0 = *(const float4*)(sinb + s * HD + d4);
    float4 s1 = *(const float4*)(sinb + s * HD + d4 + 32);

    float r0x = v0.x * c0.x - v1.x * s0.x;
    float r0y = v0.y * c0.y - v1.y * s0.y;
    float r0z = v0.z * c0.z - v1.z * s0.z;
    float r0w = v0.w * c0.w - v1.w * s0.w;
    float r1x = v1.x * c1.x + v0.x * s1.x;
    float r1y = v1.y * c1.y + v0.y * s1.y;
    float r1z = v1.z * c1.z + v0.z * s1.z;
    float r1w = v1.w * c1.w + v0.w * s1.w;

    size_t base = (size_t)bs * nheads * HD + (size_t)hh * HD;

    __nv_bfloat162 h0a = __float22bfloat162_rn(make_float2(r0x, r0y));
    __nv_bfloat162 h0b = __float22bfloat162_rn(make_float2(r0z, r0w));
    __nv_bfloat162 h1a = __float22bfloat162_rn(make_float2(r1x, r1y));
    __nv_bfloat162 h1b = __float22bfloat162_rn(make_float2(r1z, r1w));
    *(uint2*)(th + base + d4)      = make_uint2(*(uint32_t*)&h0a, *(uint32_t*)&h0b);
    *(uint2*)(th + base + d4 + 32) = make_uint2(*(uint32_t*)&h1a, *(uint32_t*)&h1b);

    __nv_bfloat162 l0a = __float22bfloat162_rn(make_float2(
        r0x - __bfloat162float(h0a.x), r0y - __bfloat162float(h0a.y)));
    __nv_bfloat162 l0b = __float22bfloat162_rn(make_float2(
        r0z - __bfloat162float(h0b.x), r0w - __bfloat162float(h0b.y)));
    __nv_bfloat162 l1a = __float22bfloat162_rn(make_float2(
        r1x - __bfloat162float(h1a.x), r1y - __bfloat162float(h1a.y)));
    __nv_bfloat162 l1b = __float22bfloat162_rn(make_float2(
        r1z - __bfloat162float(h1b.x), r1w - __bfloat162float(h1b.y)));
    *(uint2*)(tl + base + d4)      = make_uint2(*(uint32_t*)&l0a, *(uint32_t*)&l0b);
    *(uint2*)(tl + base + d4 + 32) = make_uint2(*(uint32_t*)&l1a, *(uint32_t*)&l1b);
}

// ---------------------------------------------------------------------------
// HMMA bf16x3 flash attention, causal, GQA.
// BLOCK_M=128 (8 warps), BLOCK_N=64; ldsm4 B-fragments; LPT (reversed qt).
// ---------------------------------------------------------------------------
#define FSTR 72
#define FTILE64 (64 * FSTR * 2)
#define FQ_TILE (128 * FSTR * 2)
#define FQ_H 0
#define FQ_L FQ_TILE
#define FSTG(st) (2 * FQ_TILE + (st) * 4 * FTILE64)
#define FLASH_SMEM (2 * FQ_TILE + 2 * 4 * FTILE64)   // 110592 B

__global__ __launch_bounds__(256) void flash_hmma_kernel(
    const __nv_bfloat16* __restrict__ Qh, const __nv_bfloat16* __restrict__ Ql,
    const __nv_bfloat16* __restrict__ Kh, const __nv_bfloat16* __restrict__ Kl,
    const __nv_bfloat16* __restrict__ Vth, const __nv_bfloat16* __restrict__ Vtl,
    __nv_bfloat16* __restrict__ Oh, __nv_bfloat16* __restrict__ Ol)
{
    extern __shared__ __align__(128) char smem[];
    const uint32_t sb = smem_u32(smem);
    const int tid = threadIdx.x;
    const int wid = tid >> 5;
    const int lane = tid & 31;
    const int qt = gridDim.x - 1 - blockIdx.x;   // LPT: heavy tiles first
    const int h  = blockIdx.y;
    const int b  = blockIdx.z;
    const int q0 = qt * 128;
    const int khead = h >> 2;
    const int warp_m = wid * 16;

    const int er = lane >> 2;
    const int ec = (lane & 3) * 2;
    const int a_r = lane & 15;
    const int a_c = (lane >> 4) * 8;
    const int g4 = lane >> 3;
    const int b4_r = (g4 >> 1) * 8 + (lane & 7);
    const int b4_c = (g4 & 1) * 8;

    const __nv_bfloat16* qh_g = Qh + ((size_t)(b * SS + q0) * NH + h) * HD;
    const __nv_bfloat16* ql_g = Ql + ((size_t)(b * SS + q0) * NH + h) * HD;
    const __nv_bfloat16* kh_g = Kh + ((size_t)b * SS * NKH + khead) * HD;
    const __nv_bfloat16* kl_g = Kl + ((size_t)b * SS * NKH + khead) * HD;
    const __nv_bfloat16* vth_g = Vth + (size_t)(b * NKH + khead) * HD * SS;
    const __nv_bfloat16* vtl_g = Vtl + (size_t)(b * NKH + khead) * HD * SS;

    auto load_tile64 = [&](const __nv_bfloat16* g, size_t rstride, uint32_t sofs) {
#pragma unroll
        for (int it = 0; it < 2; it++) {
            int ch = tid + it * 256;
            int r = ch >> 3;
            int q8 = ch & 7;
            CP_ASYNC16(sb + sofs + (r * FSTR + q8 * 8) * 2,
                       g + (size_t)r * rstride + q8 * 8);
        }
    };
    auto load_q = [&](const __nv_bfloat16* g, uint32_t sofs) {
#pragma unroll
        for (int it = 0; it < 4; it++) {
            int ch = tid + it * 256;
            int r = ch >> 3;
            int q8 = ch & 7;
            CP_ASYNC16(sb + sofs + (r * FSTR + q8 * 8) * 2,
                       g + (size_t)r * (NH * HD) + q8 * 8);
        }
    };

    load_q(qh_g, FQ_H);
    load_q(ql_g, FQ_L);
    load_tile64(kh_g, NKH * HD, FSTG(0) + 0 * FTILE64);
    load_tile64(kl_g, NKH * HD, FSTG(0) + 1 * FTILE64);
    load_tile64(vth_g, SS, FSTG(0) + 2 * FTILE64);
    load_tile64(vtl_g, SS, FSTG(0) + 3 * FTILE64);
    CP_COMMIT();

    float m[2] = {-1e30f, -1e30f};
    float l[2] = {0.0f, 0.0f};
    float acc[8][4];
#pragma unroll
    for (int i = 0; i < 8; i++)
#pragma unroll
        for (int r = 0; r < 4; r++) acc[i][r] = 0.0f;

    const int kt_end = 2 * qt + 1;

    for (int kt = 0; kt <= kt_end; kt++) {
        const int st = kt & 1;
        if (kt < kt_end) {
            const int kn = (kt + 1) * 64;
            load_tile64(kh_g + (size_t)kn * NKH * HD, NKH * HD, FSTG(st ^ 1) + 0 * FTILE64);
            load_tile64(kl_g + (size_t)kn * NKH * HD, NKH * HD, FSTG(st ^ 1) + 1 * FTILE64);
            load_tile64(vth_g + kn, SS, FSTG(st ^ 1) + 2 * FTILE64);
            load_tile64(vtl_g + kn, SS, FSTG(st ^ 1) + 3 * FTILE64);
            CP_COMMIT();
            CP_WAIT(1);
        } else {
            CP_WAIT(0);
        }
        __syncthreads();

        const int row_lo = q0 + warp_m;
        const bool any  = (kt * 64     <= row_lo + 15);
        const bool full = (kt * 64 + 63 <= row_lo);

        if (any) {
            const uint32_t sKh = sb + FSTG(st) + 0 * FTILE64;
            const uint32_t sKl = sb + FSTG(st) + 1 * FTILE64;
            const uint32_t sVh = sb + FSTG(st) + 2 * FTILE64;
            const uint32_t sVl = sb + FSTG(st) + 3 * FTILE64;

            float sf[8][4];
#pragma unroll
            for (int nf = 0; nf < 8; nf++)
#pragma unroll
                for (int r = 0; r < 4; r++) sf[nf][r] = 0.0f;

#pragma unroll
            for (int kf = 0; kf < 4; kf++) {
                const int kc = kf * 16;
                uint32_t qah[4], qal[4];
                uint32_t ad = ((warp_m + a_r) * FSTR + kc + a_c) * 2;
                ldsm4(qah[0], qah[1], qah[2], qah[3], sb + FQ_H + ad);
                ldsm4(qal[0], qal[1], qal[2], qal[3], sb + FQ_L + ad);
#pragma unroll
                for (int np = 0; np < 4; np++) {
                    uint32_t bd = ((np * 16 + b4_r) * FSTR + kc + b4_c) * 2;
                    uint32_t kbh[4], kbl[4];
                    ldsm4(kbh[0], kbh[1], kbh[2], kbh[3], sKh + bd);
                    ldsm4(kbl[0], kbl[1], kbl[2], kbl[3], sKl + bd);
                    mma_bf16(sf[np * 2],     qah, kbh);
                    mma_bf16(sf[np * 2],     qah, kbl);
                    mma_bf16(sf[np * 2],     qal, kbh);
                    mma_bf16(sf[np * 2 + 1], qah, kbh + 2);
                    mma_bf16(sf[np * 2 + 1], qah, kbl + 2);
                    mma_bf16(sf[np * 2 + 1], qal, kbh + 2);
                }
            }

            const float sc = 0.125f;
            if (!full) {
                const int i0 = row_lo + er;
#pragma unroll
                for (int nf = 0; nf < 8; nf++) {
                    int j0 = kt * 64 + nf * 8 + ec;
                    sf[nf][0] = (j0     <= i0)     ? sf[nf][0] * sc : -1e30f;
                    sf[nf][1] = (j0 + 1 <= i0)     ? sf[nf][1] * sc : -1e30f;
                    sf[nf][2] = (j0     <= i0 + 8) ? sf[nf][2] * sc : -1e30f;
                    sf[nf][3] = (j0 + 1 <= i0 + 8) ? sf[nf][3] * sc : -1e30f;
                }
            } else {
#pragma unroll
                for (int nf = 0; nf < 8; nf++)
#pragma unroll
                    for (int r = 0; r < 4; r++) sf[nf][r] *= sc;
            }

            float rmax0 = -1e30f, rmax1 = -1e30f;
#pragma unroll
            for (int nf = 0; nf < 8; nf++) {
                rmax0 = fmaxf(rmax0, fmaxf(sf[nf][0], sf[nf][1]));
                rmax1 = fmaxf(rmax1, fmaxf(sf[nf][2], sf[nf][3]));
            }
            rmax0 = fmaxf(rmax0, __shfl_xor_sync(0xffffffffu, rmax0, 1));
            rmax0 = fmaxf(rmax0, __shfl_xor_sync(0xffffffffu, rmax0, 2));
            rmax1 = fmaxf(rmax1, __shfl_xor_sync(0xffffffffu, rmax1, 1));
            rmax1 = fmaxf(rmax1, __shfl_xor_sync(0xffffffffu, rmax1, 2));

            float nm0 = fmaxf(m[0], rmax0), nm1 = fmaxf(m[1], rmax1);
            float al0 = __expf(m[0] - nm0), al1 = __expf(m[1] - nm1);
            m[0] = nm0; m[1] = nm1;

            float sum0 = 0.0f, sum1 = 0.0f;
#pragma unroll
            for (int nf = 0; nf < 8; nf++) {
                sf[nf][0] = __expf(sf[nf][0] - nm0);
                sf[nf][1] = __expf(sf[nf][1] - nm0);
                sf[nf][2] = __expf(sf[nf][2] - nm1);
                sf[nf][3] = __expf(sf[nf][3] - nm1);
                sum0 += sf[nf][0] + sf[nf][1];
                sum1 += sf[nf][2] + sf[nf][3];
            }
            sum0 += __shfl_xor_sync(0xffffffffu, sum0, 1);
            sum0 += __shfl_xor_sync(0xffffffffu, sum0, 2);
            sum1 += __shfl_xor_sync(0xffffffffu, sum1, 1);
            sum1 += __shfl_xor_sync(0xffffffffu, sum1, 2);
            l[0] = l[0] * al0 + sum0;
            l[1] = l[1] * al1 + sum1;
#pragma unroll
            for (int i = 0; i < 8; i++) {
                acc[i][0] *= al0; acc[i][1] *= al0;
                acc[i][2] *= al1; acc[i][3] *= al1;
            }

            uint32_t pha[4][4], pla[4][4];
#pragma unroll
            for (int kf = 0; kf < 4; kf++) {
#pragma unroll
                for (int half = 0; half < 2; half++) {
                    const float* s2 = sf[kf * 2 + half];
                    __nv_bfloat162 h01 = __float22bfloat162_rn(make_float2(s2[0], s2[1]));
                    __nv_bfloat162 h23 = __float22bfloat162_rn(make_float2(s2[2], s2[3]));
                    __nv_bfloat162 l01 = __float22bfloat162_rn(make_float2(
                        s2[0] - __bfloat162float(h01.x), s2[1] - __bfloat162float(h01.y)));
                    __nv_bfloat162 l23 = __float22bfloat162_rn(make_float2(
                        s2[2] - __bfloat162float(h23.x), s2[3] - __bfloat162float(h23.y)));
                    pha[kf][half * 2 + 0] = *(uint32_t*)&h01;
                    pha[kf][half * 2 + 1] = *(uint32_t*)&h23;
                    pla[kf][half * 2 + 0] = *(uint32_t*)&l01;
                    pla[kf][half * 2 + 1] = *(uint32_t*)&l23;
                }
            }

#pragma unroll
            for (int kf = 0; kf < 4; kf++) {
#pragma unroll
                for (int np = 0; np < 4; np++) {
                    uint32_t bd = ((np * 16 + b4_r) * FSTR + kf * 16 + b4_c) * 2;
                    uint32_t vbh[4], vbl[4];
                    ldsm4(vbh[0], vbh[1], vbh[2], vbh[3], sVh + bd);
                    ldsm4(vbl[0], vbl[1], vbl[2], vbl[3], sVl + bd);
                    mma_bf16(acc[np * 2],     pha[kf], vbh);
                    mma_bf16(acc[np * 2],     pha[kf], vbl);
                    mma_bf16(acc[np * 2],     pla[kf], vbh);
                    mma_bf16(acc[np * 2 + 1], pha[kf], vbh + 2);
                    mma_bf16(acc[np * 2 + 1], pha[kf], vbl + 2);
                    mma_bf16(acc[np * 2 + 1], pla[kf], vbh + 2);
                }
            }
        }
        __syncthreads();
    }

    float inv0 = 1.0f / l[0], inv1 = 1.0f / l[1];
#pragma unroll
    for (int nf = 0; nf < 8; nf++) {
        size_t o0 = ((size_t)(b * SS + q0 + warp_m + er) * NH + h) * HD + nf * 8 + ec;
        size_t o1 = ((size_t)(b * SS + q0 + warp_m + er + 8) * NH + h) * HD + nf * 8 + ec;
        float v00 = acc[nf][0] * inv0, v01 = acc[nf][1] * inv0;
        float v10 = acc[nf][2] * inv1, v11 = acc[nf][3] * inv1;
        __nv_bfloat162 h0 = __float22bfloat162_rn(make_float2(v00, v01));
        __nv_bfloat162 h1 = __float22bfloat162_rn(make_float2(v10, v11));
        __nv_bfloat162 l0 = __float22bfloat162_rn(make_float2(
            v00 - __bfloat162float(h0.x), v01 - __bfloat162float(h0.y)));
        __nv_bfloat162 l1 = __float22bfloat162_rn(make_float2(
            v10 - __bfloat162float(h1.x), v11 - __bfloat162float(h1.y)));
        *(uint32_t*)(Oh + o0) = *(uint32_t*)&h0;
        *(uint32_t*)(Oh + o1) = *(uint32_t*)&h1;
        *(uint32_t*)(Ol + o0) = *(uint32_t*)&l0;
        *(uint32_t*)(Ol + o1) = *(uint32_t*)&l1;
    }
}

// ---------------------------------------------------------------------------
extern "C" void kernel_launch(void* const* d_in, const int* in_sizes, int n_in,
                              void* d_out, int out_size)
{
    const float* x    = (const float*)d_in[0];
    const float* cosb = (const float*)d_in[1];
    const float* sinb = (const float*)d_in[2];
    const float* wq   = (const float*)d_in[3];
    const float* wk   = (const float*)d_in[4];
    const float* wv   = (const float*)d_in[5];
    const float* wo   = (const float*)d_in[6];
    float* out = (float*)d_out;

    float* qkv;
    cudaGetSymbolAddress((void**)&qkv, g_qkv);

    __nv_bfloat16 *xh, *xl, *oh, *ol;
    __nv_bfloat16 *wqkvh, *wqkvl, *woh, *wol;
    __nv_bfloat16 *qh, *ql, *kh2, *kl2, *vth, *vtl;
    cudaGetSymbolAddress((void**)&xh, g_xh);
    cudaGetSymbolAddress((void**)&xl, g_xl);
    cudaGetSymbolAddress((void**)&oh, g_oh);
    cudaGetSymbolAddress((void**)&ol, g_ol);
    cudaGetSymbolAddress((void**)&wqkvh, g_wqkvh);
    cudaGetSymbolAddress((void**)&wqkvl, g_wqkvl);
    cudaGetSymbolAddress((void**)&woh, g_woh);
    cudaGetSymbolAddress((void**)&wol, g_wol);
    cudaGetSymbolAddress((void**)&qh, g_qh);
    cudaGetSymbolAddress((void**)&ql, g_ql);
    cudaGetSymbolAddress((void**)&kh2, g_kh2);
    cudaGetSymbolAddress((void**)&kl2, g_kl2);
    cudaGetSymbolAddress((void**)&vth, g_vth);
    cudaGetSymbolAddress((void**)&vtl, g_vtl);

    cudaFuncSetAttribute(gemm_bf16x3_kernel,
                         cudaFuncAttributeMaxDynamicSharedMemorySize, GEMM_SMEM);
    cudaFuncSetAttribute(flash_hmma_kernel,
                         cudaFuncAttributeMaxDynamicSharedMemorySize, FLASH_SMEM);

    const int M = BB * SS;  // 4096

    // Split activations; fused weight prep (all 4 weights, one launch)
    {
        int n4 = M * DMODEL / 4;
        split_kernel<<<(n4 + 255) / 256, 256>>>(
            (const float4*)x, (__nv_bfloat162*)xh, (__nv_bfloat162*)xl, n4);
        weight_prep_kernel<<<2560, dim3(32, 8)>>>(
            wq, wk, wv, wo, wqkvh, wqkvl, woh, wol);
    }

    // Fused QKV projection (HMMA bf16x3): [4096][1536]
    gemm_bf16x3_kernel<<<dim3(NQKV / 128, M / 128), 256, GEMM_SMEM>>>(
        xh, xl, wqkvh, wqkvl, qkv, M, NQKV, DMODEL);

    // Fused RoPE + split (q and k); V transpose + split
    {
        int ntot = BB * SS * NH * 8 + BB * SS * NKH * 8;
        rope_split_qk_kernel<<<(ntot + 255) / 256, 256>>>(
            qkv, cosb, sinb, qh, ql, kh2, kl2);
        dim3 blk(32, 8);
        vtrans_split_kernel<<<dim3(SS / 32, HD / 32, BB * NKH), blk>>>(qkv, vth, vtl);
    }

    // Causal GQA flash attention (HMMA bf16x3)
    flash_hmma_kernel<<<dim3(SS / 128, NH, BB), 256, FLASH_SMEM>>>(
        qh, ql, kh2, kl2, vth, vtl, oh, ol);

    // Output projection (HMMA bf16x3)
    gemm_bf16x3_kernel<<<dim3(DMODEL / 128, M / 128), 256, GEMM_SMEM>>>(
        oh, ol, woh, wol, out, M, DMODEL, DMODEL);
}